// round 6
// baseline (speedup 1.0000x reference)
#include <cuda_runtime.h>
#include <cuda_bf16.h>
#include <math.h>
#include <stdint.h>

// ---------------- problem constants ----------------
namespace {
constexpr int B_  = 8;
constexpr int P_  = 16;
constexpr int HOR = 10;
constexpr int NO_ = 128;
constexpr int NR_ = 8;
constexpr int D_  = 768;
constexpr int NH_ = 12;
constexpr int HD_ = 64;
constexpr int F_  = 3072;
constexpr int L_  = 12;
constexpr int TPS = NO_ + NR_;          // 136
constexpr int T_  = P_ + HOR * TPS;     // 1376
constexpr int M_  = B_ * T_;            // 11008
constexpr float LN_EPS = 1e-6f;
constexpr float ATT_SCALE = 0.125f;     // 1/sqrt(64)

// GEMM tiling (warp-mma, split-bf16), 512 threads, 4x4 warp grid
constexpr int BM = 128;
constexpr int BN = 128;
constexpr int BK = 32;
constexpr int RS = 40;                   // SMEM row stride in bf16 (80B), conflict-free ldmatrix
constexpr int TILE_B = BM * RS * 2;      // 10240 bytes per operand tile
constexpr int STAGE_B = 4 * TILE_B;      // Ahi,Alo,Bhi,Blo = 40960
constexpr int SMEM_GEMM = 2 * STAGE_B;   // 81920

// attention smem layout (bf16 units unless noted)
constexpr int ARS   = 72;                // 144B row stride, conflict-free
constexpr int AT_QH = 0;
constexpr int AT_QL = 1 * 64 * ARS;
constexpr int AT_KH = 2 * 64 * ARS;
constexpr int AT_KL = 3 * 64 * ARS;
constexpr int AT_VH = 4 * 64 * ARS;
constexpr int AT_VL = 5 * 64 * ARS;
constexpr int AT_CODE_B = 6 * 64 * ARS * 2;     // byte offset of key codes
constexpr int ATTN_SMEM = AT_CODE_B + 64 * 4;   // 55552 bytes
}

// ---------------- scratch (device globals: no cudaMalloc allowed) ----------------
__device__ float g_x[(size_t)M_ * D_];
__device__ __nv_bfloat16 g_y_hi  [(size_t)M_ * D_];
__device__ __nv_bfloat16 g_y_lo  [(size_t)M_ * D_];
__device__ __nv_bfloat16 g_qkv_hi[(size_t)M_ * 3 * D_];
__device__ __nv_bfloat16 g_qkv_lo[(size_t)M_ * 3 * D_];
__device__ __nv_bfloat16 g_att_hi[(size_t)M_ * D_];
__device__ __nv_bfloat16 g_att_lo[(size_t)M_ * D_];
__device__ __nv_bfloat16 g_ffn_hi[(size_t)M_ * F_];
__device__ __nv_bfloat16 g_ffn_lo[(size_t)M_ * F_];
__device__ __nv_bfloat16 g_wqkvT_hi[(size_t)L_ * 3 * D_ * D_];
__device__ __nv_bfloat16 g_wqkvT_lo[(size_t)L_ * 3 * D_ * D_];
__device__ __nv_bfloat16 g_woT_hi  [(size_t)L_ * D_ * D_];
__device__ __nv_bfloat16 g_woT_lo  [(size_t)L_ * D_ * D_];
__device__ __nv_bfloat16 g_w1T_hi  [(size_t)L_ * F_ * D_];
__device__ __nv_bfloat16 g_w1T_lo  [(size_t)L_ * F_ * D_];
__device__ __nv_bfloat16 g_w2T_hi  [(size_t)L_ * D_ * F_];
__device__ __nv_bfloat16 g_w2T_lo  [(size_t)L_ * D_ * F_];

// ---------------- mma helpers ----------------
__device__ __forceinline__ unsigned smem_u32(const void* p) {
    return (unsigned)__cvta_generic_to_shared(p);
}
__device__ __forceinline__ void ldsm_x4(unsigned* r, unsigned addr) {
    asm volatile("ldmatrix.sync.aligned.m8n8.x4.shared.b16 {%0,%1,%2,%3}, [%4];"
                 : "=r"(r[0]), "=r"(r[1]), "=r"(r[2]), "=r"(r[3]) : "r"(addr));
}
__device__ __forceinline__ void ldsm_x4t(unsigned* r, unsigned addr) {
    asm volatile("ldmatrix.sync.aligned.m8n8.x4.trans.shared.b16 {%0,%1,%2,%3}, [%4];"
                 : "=r"(r[0]), "=r"(r[1]), "=r"(r[2]), "=r"(r[3]) : "r"(addr));
}
__device__ __forceinline__ void mma_bf16(float* c, const unsigned* a, const unsigned* b) {
    asm volatile(
        "mma.sync.aligned.m16n8k16.row.col.f32.bf16.bf16.f32 "
        "{%0,%1,%2,%3}, {%4,%5,%6,%7}, {%8,%9}, {%0,%1,%2,%3};"
        : "+f"(c[0]), "+f"(c[1]), "+f"(c[2]), "+f"(c[3])
        : "r"(a[0]), "r"(a[1]), "r"(a[2]), "r"(a[3]), "r"(b[0]), "r"(b[1]));
}
__device__ __forceinline__ unsigned pack_bf2(__nv_bfloat16 a, __nv_bfloat16 b) {
    __nv_bfloat162 t(a, b);
    return *(unsigned*)&t;
}
__device__ __forceinline__ void split2(float v, __nv_bfloat16& h, __nv_bfloat16& l) {
    h = __float2bfloat16(v);
    l = __float2bfloat16(v - __bfloat162float(h));
}

// ---------------- misc helpers ----------------
__device__ __forceinline__ float gelu_tanh(float x) {
    float x3 = x * x * x;
    return 0.5f * x * (1.0f + tanhf(0.7978845608028654f * (x + 0.044715f * x3)));
}
__device__ __forceinline__ int tok_group(int i) {
    if (i < P_) return 0;
    return (((i - P_) % TPS) < NO_) ? 1 : 2;
}
__device__ __forceinline__ int tok_ts(int i) {
    return (i < P_) ? -1 : (i - P_) / TPS;
}
__device__ __forceinline__ bool allow_code(int gq, int tq, int kc) {
    int gk = kc & 3;
    int tk = kc >> 2;
    if (gk == 0) return true;
    if (gq == 0) return false;
    if (tk > tq) return false;
    return (gk == 1) || (gq == 2);
}

// ---------------- assemble ----------------
__global__ void assemble_kernel(const float* __restrict__ prefix,
                                const float* __restrict__ obs,
                                const float* __restrict__ rdo) {
    for (int idx = blockIdx.x * blockDim.x + threadIdx.x;
         idx < M_ * D_; idx += gridDim.x * blockDim.x) {
        int d = idx % D_;
        int bt = idx / D_;
        int t = bt % T_;
        int b = bt / T_;
        float v;
        if (t < P_) {
            v = prefix[((size_t)b * P_ + t) * D_ + d];
        } else {
            int tt = t - P_;
            int ho = tt / TPS;
            int r  = tt % TPS;
            if (r < NO_)
                v = obs[(((size_t)b * HOR + ho) * NO_ + r) * D_ + d];
            else
                v = rdo[(((size_t)b * HOR + ho) * NR_ + (r - NO_)) * D_ + d];
        }
        g_x[idx] = v;
    }
}

// ---------------- weight transpose + split ----------------
__global__ void wsplit_kernel(const float* __restrict__ src,
                              __nv_bfloat16* __restrict__ hiT,
                              __nv_bfloat16* __restrict__ loT, int R, int C) {
    __shared__ float t[32][33];
    int cb = blockIdx.x * 32, rb = blockIdx.y * 32;
    int tx = threadIdx.x, ty = threadIdx.y;
    #pragma unroll
    for (int i = 0; i < 32; i += 8)
        t[ty + i][tx] = src[(size_t)(rb + ty + i) * C + cb + tx];
    __syncthreads();
    #pragma unroll
    for (int i = 0; i < 32; i += 8) {
        float v = t[tx][ty + i];
        __nv_bfloat16 h, l;
        split2(v, h, l);
        size_t o = (size_t)(cb + ty + i) * R + rb + tx;
        hiT[o] = h;
        loT[o] = l;
    }
}

// ---------------- layernorm ----------------
__device__ __forceinline__ float block_reduce_sum(float v, float* red) {
    int lane = threadIdx.x & 31;
    int wid  = threadIdx.x >> 5;
    #pragma unroll
    for (int o = 16; o; o >>= 1) v += __shfl_down_sync(0xffffffffu, v, o);
    if (lane == 0) red[wid] = v;
    __syncthreads();
    if (threadIdx.x < 32) {
        float t = (threadIdx.x < 8) ? red[threadIdx.x] : 0.0f;
        #pragma unroll
        for (int o = 4; o; o >>= 1) t += __shfl_down_sync(0xffffffffu, t, o);
        if (threadIdx.x == 0) red[32] = t;
    }
    __syncthreads();
    return red[32];
}

__global__ void ln_kernel(const float* __restrict__ x,
                          const float* __restrict__ s,
                          const float* __restrict__ b,
                          float* __restrict__ y) {
    __shared__ float red[33];
    int row = blockIdx.x;
    const float* xp = x + (size_t)row * D_;
    float v0 = xp[threadIdx.x];
    float v1 = xp[threadIdx.x + 256];
    float v2 = xp[threadIdx.x + 512];
    float mu = block_reduce_sum(v0 + v1 + v2, red) * (1.0f / D_);
    float d0 = v0 - mu, d1 = v1 - mu, d2 = v2 - mu;
    float var = block_reduce_sum(d0 * d0 + d1 * d1 + d2 * d2, red) * (1.0f / D_);
    float inv = rsqrtf(var + LN_EPS);
    float* yp = y + (size_t)row * D_;
    yp[threadIdx.x      ] = d0 * inv * s[threadIdx.x      ] + b[threadIdx.x      ];
    yp[threadIdx.x + 256] = d1 * inv * s[threadIdx.x + 256] + b[threadIdx.x + 256];
    yp[threadIdx.x + 512] = d2 * inv * s[threadIdx.x + 512] + b[threadIdx.x + 512];
}

__global__ void ln_split_kernel(const float* __restrict__ x,
                                const float* __restrict__ s,
                                const float* __restrict__ b,
                                __nv_bfloat16* __restrict__ yhi,
                                __nv_bfloat16* __restrict__ ylo) {
    __shared__ float red[33];
    int row = blockIdx.x;
    const float* xp = x + (size_t)row * D_;
    float v0 = xp[threadIdx.x];
    float v1 = xp[threadIdx.x + 256];
    float v2 = xp[threadIdx.x + 512];
    float mu = block_reduce_sum(v0 + v1 + v2, red) * (1.0f / D_);
    float d0 = v0 - mu, d1 = v1 - mu, d2 = v2 - mu;
    float var = block_reduce_sum(d0 * d0 + d1 * d1 + d2 * d2, red) * (1.0f / D_);
    float inv = rsqrtf(var + LN_EPS);
    size_t base = (size_t)row * D_;
    #pragma unroll
    for (int i = 0; i < 3; i++) {
        int c = threadIdx.x + i * 256;
        float dv = (i == 0 ? d0 : (i == 1 ? d1 : d2));
        float v = dv * inv * s[c] + b[c];
        __nv_bfloat16 h, l;
        split2(v, h, l);
        yhi[base + c] = h;
        ylo[base + c] = l;
    }
}

// ---------------- split-bf16 warp-mma GEMM (512 threads, 4x4 warp grid) ----------------
// C[M,N] = (Ahi+Alo)[M,K] @ (Whi+Wlo)[N,K]^T + bias
// EPI 0: write split bf16 ; EPI 1: gelu -> split bf16 ; EPI 2: +R -> fp32
template <int EPI>
__global__ __launch_bounds__(512, 1) void wmma_gemm(
    const __nv_bfloat16* __restrict__ Ahi, const __nv_bfloat16* __restrict__ Alo,
    const __nv_bfloat16* __restrict__ Whi, const __nv_bfloat16* __restrict__ Wlo,
    const float* __restrict__ bias, const float* __restrict__ R,
    float* __restrict__ C,
    __nv_bfloat16* __restrict__ Chi, __nv_bfloat16* __restrict__ Clo,
    int Ndim, int Kdim) {
    extern __shared__ char smem[];
    const unsigned sbase = smem_u32(smem);
    const int tid = threadIdx.x;
    const int lane = tid & 31;
    const int wid = tid >> 5;
    const int warp_m = wid & 3;          // 4 warp rows (32 M each)
    const int warp_n = wid >> 2;         // 4 warp cols (32 N each)
    const int bm = blockIdx.y * BM;
    const int bn = blockIdx.x * BN;
    const int NK = Kdim / BK;

    // staging registers: 1 chunk per thread per tile
    uint4 ah, al, bh, bl;
    const int r_ = tid >> 2, cc_ = tid & 3;
    const unsigned so = (unsigned)(r_ * (RS * 2) + cc_ * 16);

    auto load_tile = [&](int k0) {
        size_t ao = (size_t)(bm + r_) * Kdim + k0 + 8 * cc_;
        size_t bo = (size_t)(bn + r_) * Kdim + k0 + 8 * cc_;
        ah = *(const uint4*)(Ahi + ao);
        al = *(const uint4*)(Alo + ao);
        bh = *(const uint4*)(Whi + bo);
        bl = *(const uint4*)(Wlo + bo);
    };
    auto store_tile = [&](int s) {
        char* base = smem + s * STAGE_B;
        *(uint4*)(base + so)              = ah;
        *(uint4*)(base + TILE_B + so)     = al;
        *(uint4*)(base + 2 * TILE_B + so) = bh;
        *(uint4*)(base + 3 * TILE_B + so) = bl;
    };

    const unsigned a_base = (unsigned)((warp_m * 32 + (lane & 15)) * (RS * 2) + (lane >> 4) * 16);
    const unsigned b_row = (unsigned)(warp_n * 32 + (lane & 7) + ((lane >> 4) << 3));
    const unsigned b_base = (unsigned)(b_row * (RS * 2) + (((lane >> 3) & 1) * 16));

    float acc[2][4][4];
    #pragma unroll
    for (int mt = 0; mt < 2; mt++)
        #pragma unroll
        for (int nt = 0; nt < 4; nt++)
            #pragma unroll
            for (int r = 0; r < 4; r++) acc[mt][nt][r] = 0.0f;

    load_tile(0);
    for (int i = 0; i < NK; i++) {
        const int s = i & 1;
        store_tile(s);
        if (i + 1 < NK) load_tile((i + 1) * BK);
        __syncthreads();

        const unsigned tAhi = sbase + s * STAGE_B;
        const unsigned tAlo = tAhi + TILE_B;
        const unsigned tBhi = tAlo + TILE_B;
        const unsigned tBlo = tBhi + TILE_B;

        #pragma unroll
        for (int ks = 0; ks < 2; ks++) {
            unsigned fah[2][4], fal[2][4];
            unsigned fbh[2][4], fbl[2][4];
            #pragma unroll
            for (int mt = 0; mt < 2; mt++) {
                unsigned ao = a_base + (unsigned)(mt * 16 * (RS * 2) + ks * 32);
                ldsm_x4(fah[mt], tAhi + ao);
                ldsm_x4(fal[mt], tAlo + ao);
            }
            #pragma unroll
            for (int pr = 0; pr < 2; pr++) {
                unsigned bo = b_base + (unsigned)(pr * 16 * (RS * 2) + ks * 32);
                ldsm_x4(fbh[pr], tBhi + bo);
                ldsm_x4(fbl[pr], tBlo + bo);
            }
            #pragma unroll
            for (int mt = 0; mt < 2; mt++) {
                #pragma unroll
                for (int nt = 0; nt < 4; nt++) {
                    const unsigned* bH = &fbh[nt >> 1][(nt & 1) * 2];
                    const unsigned* bL = &fbl[nt >> 1][(nt & 1) * 2];
                    mma_bf16(acc[mt][nt], fah[mt], bH);
                    mma_bf16(acc[mt][nt], fah[mt], bL);
                    mma_bf16(acc[mt][nt], fal[mt], bH);
                }
            }
        }
        __syncthreads();
    }

    // ---- epilogue ----
    const int g = lane >> 2, tg = lane & 3;
    #pragma unroll
    for (int mt = 0; mt < 2; mt++) {
        #pragma unroll
        for (int nt = 0; nt < 4; nt++) {
            int row0 = bm + warp_m * 32 + mt * 16 + g;
            int col  = bn + warp_n * 32 + nt * 8 + tg * 2;
            float2 bv = *(const float2*)(bias + col);
            float c0 = acc[mt][nt][0] + bv.x;
            float c1 = acc[mt][nt][1] + bv.y;
            float c2 = acc[mt][nt][2] + bv.x;
            float c3 = acc[mt][nt][3] + bv.y;
            size_t o0 = (size_t)row0 * Ndim + col;
            size_t o1 = o0 + (size_t)8 * Ndim;
            if (EPI == 2) {
                float2 r0 = *(const float2*)(R + o0);
                float2 r1 = *(const float2*)(R + o1);
                c0 += r0.x; c1 += r0.y; c2 += r1.x; c3 += r1.y;
                *(float2*)(C + o0) = make_float2(c0, c1);
                *(float2*)(C + o1) = make_float2(c2, c3);
            } else {
                if (EPI == 1) {
                    c0 = gelu_tanh(c0); c1 = gelu_tanh(c1);
                    c2 = gelu_tanh(c2); c3 = gelu_tanh(c3);
                }
                __nv_bfloat16 h0, l0v, h1, l1v, h2, l2v, h3, l3v;
                split2(c0, h0, l0v); split2(c1, h1, l1v);
                split2(c2, h2, l2v); split2(c3, h3, l3v);
                *(unsigned*)(Chi + o0) = pack_bf2(h0, h1);
                *(unsigned*)(Clo + o0) = pack_bf2(l0v, l1v);
                *(unsigned*)(Chi + o1) = pack_bf2(h2, h3);
                *(unsigned*)(Clo + o1) = pack_bf2(l2v, l3v);
            }
        }
    }
}

// ---------------- tensor-core flash attention (split bf16, R4 form) ----------------
__global__ __launch_bounds__(128) void attn_mma(
    const __nv_bfloat16* __restrict__ qh_, const __nv_bfloat16* __restrict__ ql_,
    __nv_bfloat16* __restrict__ oh_, __nv_bfloat16* __restrict__ ol_) {
    extern __shared__ char smem[];
    __nv_bfloat16* sb = (__nv_bfloat16*)smem;
    int* kcode = (int*)(smem + AT_CODE_B);
    const unsigned sbase = smem_u32(smem);
    const int h = blockIdx.y, b = blockIdx.z;
    const int q0 = blockIdx.x * 64;
    const int tid = threadIdx.x;
    const int lane = tid & 31;
    const int warp = tid >> 5;
    const int tg2 = (lane & 3) * 2;

    for (int idx = tid; idx < 64 * 8; idx += 128) {
        int r = idx >> 3, c = idx & 7;
        int gr = min(q0 + r, T_ - 1);
        size_t src = ((size_t)(b * T_ + gr)) * (3 * D_) + h * HD_ + c * 8;
        *(uint4*)&sb[AT_QH + r * ARS + c * 8] = *(const uint4*)(qh_ + src);
        *(uint4*)&sb[AT_QL + r * ARS + c * 8] = *(const uint4*)(ql_ + src);
    }
    __syncthreads();

    unsigned qfh[4][4], qfl[4][4];
    {
        unsigned rowoff = (unsigned)((warp * 16 + (lane & 15)) * (ARS * 2)) + (lane >> 4) * 16;
        #pragma unroll
        for (int ks = 0; ks < 4; ks++) {
            ldsm_x4(qfh[ks], sbase + AT_QH * 2 + rowoff + ks * 32);
            ldsm_x4(qfl[ks], sbase + AT_QL * 2 + rowoff + ks * 32);
        }
    }

    const int r0 = q0 + warp * 16 + (lane >> 2);
    const int r1 = r0 + 8;
    const int rc0 = min(r0, T_ - 1), rc1 = min(r1, T_ - 1);
    const int gq0 = tok_group(rc0), tq0 = tok_ts(rc0);
    const int gq1 = tok_group(rc1), tq1 = tok_ts(rc1);

    float m0 = -1e30f, m1 = -1e30f, l0 = 0.0f, l1 = 0.0f;
    float o[8][4];
    #pragma unroll
    for (int nt = 0; nt < 8; nt++)
        #pragma unroll
        for (int r = 0; r < 4; r++) o[nt][r] = 0.0f;

    const int rlast = min(q0 + 63, T_ - 1);
    const int kmax = P_ + (tok_ts(rlast) + 1) * TPS;

    const unsigned kb = (unsigned)(((lane & 7) + ((lane >> 4) << 3)) * (ARS * 2)) +
                        ((lane >> 3) & 1) * 16;

    for (int k0 = 0; k0 < kmax; k0 += 64) {
        __syncthreads();
        for (int idx = tid; idx < 64 * 8; idx += 128) {
            int r = idx >> 3, c = idx & 7;
            int kr = k0 + r;
            uint4 z = make_uint4(0, 0, 0, 0);
            uint4 kvh = z, kvl = z, vvh = z, vvl = z;
            if (kr < T_) {
                size_t src = ((size_t)(b * T_ + kr)) * (3 * D_) + D_ + h * HD_ + c * 8;
                kvh = *(const uint4*)(qh_ + src);
                kvl = *(const uint4*)(ql_ + src);
                vvh = *(const uint4*)(qh_ + src + D_);
                vvl = *(const uint4*)(ql_ + src + D_);
            }
            *(uint4*)&sb[AT_KH + r * ARS + c * 8] = kvh;
            *(uint4*)&sb[AT_KL + r * ARS + c * 8] = kvl;
            *(uint4*)&sb[AT_VH + r * ARS + c * 8] = vvh;
            *(uint4*)&sb[AT_VL + r * ARS + c * 8] = vvl;
        }
        if (tid < 64) {
            int kg = k0 + tid;
            kcode[tid] = (kg < kmax && kg < T_)
                       ? ((tok_ts(kg) << 2) | tok_group(kg))
                       : ((0x3FFF << 2) | 3);
        }
        __syncthreads();

        float s[8][4];
        #pragma unroll
        for (int nt = 0; nt < 8; nt++)
            #pragma unroll
            for (int r = 0; r < 4; r++) s[nt][r] = 0.0f;

        #pragma unroll
        for (int kg = 0; kg < 4; kg++) {
            #pragma unroll
            for (int ks = 0; ks < 4; ks++) {
                unsigned kh[4], kl[4];
                unsigned addr = sbase + kb + (unsigned)(kg * 16 * (ARS * 2)) + ks * 32;
                ldsm_x4(kh, addr + AT_KH * 2);
                ldsm_x4(kl, addr + AT_KL * 2);
                #pragma unroll
                for (int half = 0; half < 2; half++) {
                    int nt = kg * 2 + half;
                    mma_bf16(s[nt], qfh[ks], &kh[half * 2]);
                    mma_bf16(s[nt], qfh[ks], &kl[half * 2]);
                    mma_bf16(s[nt], qfl[ks], &kh[half * 2]);
                }
            }
        }

        #pragma unroll
        for (int nt = 0; nt < 8; nt++) {
            int kc0 = kcode[nt * 8 + tg2];
            int kc1 = kcode[nt * 8 + tg2 + 1];
            s[nt][0] = allow_code(gq0, tq0, kc0) ? s[nt][0] * ATT_SCALE : -1e30f;
            s[nt][1] = allow_code(gq0, tq0, kc1) ? s[nt][1] * ATT_SCALE : -1e30f;
            s[nt][2] = allow_code(gq1, tq1, kc0) ? s[nt][2] * ATT_SCALE : -1e30f;
            s[nt][3] = allow_code(gq1, tq1, kc1) ? s[nt][3] * ATT_SCALE : -1e30f;
        }

        float mx0 = -1e30f, mx1 = -1e30f;
        #pragma unroll
        for (int nt = 0; nt < 8; nt++) {
            mx0 = fmaxf(mx0, fmaxf(s[nt][0], s[nt][1]));
            mx1 = fmaxf(mx1, fmaxf(s[nt][2], s[nt][3]));
        }
        mx0 = fmaxf(mx0, __shfl_xor_sync(0xffffffffu, mx0, 1));
        mx0 = fmaxf(mx0, __shfl_xor_sync(0xffffffffu, mx0, 2));
        mx1 = fmaxf(mx1, __shfl_xor_sync(0xffffffffu, mx1, 1));
        mx1 = fmaxf(mx1, __shfl_xor_sync(0xffffffffu, mx1, 2));
        float mn0 = fmaxf(m0, mx0), mn1 = fmaxf(m1, mx1);
        float corr0 = __expf(m0 - mn0), corr1 = __expf(m1 - mn1);
        m0 = mn0; m1 = mn1;
        l0 *= corr0; l1 *= corr1;
        #pragma unroll
        for (int nt = 0; nt < 8; nt++) {
            o[nt][0] *= corr0; o[nt][1] *= corr0;
            o[nt][2] *= corr1; o[nt][3] *= corr1;
        }

        #pragma unroll
        for (int kv = 0; kv < 4; kv++) {
            unsigned ph[4], pl[4];
            #pragma unroll
            for (int half = 0; half < 2; half++) {
                int nt = kv * 2 + half;
                float p0 = __expf(s[nt][0] - m0);
                float p1 = __expf(s[nt][1] - m0);
                float p2 = __expf(s[nt][2] - m1);
                float p3 = __expf(s[nt][3] - m1);
                l0 += p0 + p1;
                l1 += p2 + p3;
                __nv_bfloat16 h0, lo0, h1, lo1, h2, lo2, h3, lo3;
                split2(p0, h0, lo0); split2(p1, h1, lo1);
                split2(p2, h2, lo2); split2(p3, h3, lo3);
                ph[half * 2 + 0] = pack_bf2(h0, h1);
                ph[half * 2 + 1] = pack_bf2(h2, h3);
                pl[half * 2 + 0] = pack_bf2(lo0, lo1);
                pl[half * 2 + 1] = pack_bf2(lo2, lo3);
            }
            #pragma unroll
            for (int dg = 0; dg < 4; dg++) {
                unsigned vh[4], vl[4];
                unsigned addr = sbase + kb + (unsigned)(kv * 16 * (ARS * 2)) + dg * 32;
                ldsm_x4t(vh, addr + AT_VH * 2);
                ldsm_x4t(vl, addr + AT_VL * 2);
                #pragma unroll
                for (int half = 0; half < 2; half++) {
                    int nt = dg * 2 + half;
                    unsigned bhp[2] = {vh[half], vh[2 + half]};
                    unsigned blp[2] = {vl[half], vl[2 + half]};
                    mma_bf16(o[nt], ph, bhp);
                    mma_bf16(o[nt], ph, blp);
                    mma_bf16(o[nt], pl, bhp);
                }
            }
        }
    }

    l0 += __shfl_xor_sync(0xffffffffu, l0, 1);
    l0 += __shfl_xor_sync(0xffffffffu, l0, 2);
    l1 += __shfl_xor_sync(0xffffffffu, l1, 1);
    l1 += __shfl_xor_sync(0xffffffffu, l1, 2);
    float li0 = 1.0f / l0, li1 = 1.0f / l1;

    #pragma unroll
    for (int nt = 0; nt < 8; nt++) {
        int d = h * HD_ + nt * 8 + tg2;
        if (r0 < T_) {
            size_t off = ((size_t)(b * T_ + r0)) * D_ + d;
            float v0 = o[nt][0] * li0, v1 = o[nt][1] * li0;
            __nv_bfloat16 h0, lo0, h1, lo1;
            split2(v0, h0, lo0); split2(v1, h1, lo1);
            *(unsigned*)(oh_ + off) = pack_bf2(h0, h1);
            *(unsigned*)(ol_ + off) = pack_bf2(lo0, lo1);
        }
        if (r1 < T_) {
            size_t off = ((size_t)(b * T_ + r1)) * D_ + d;
            float v2 = o[nt][2] * li1, v3 = o[nt][3] * li1;
            __nv_bfloat16 h2, lo2, h3, lo3;
            split2(v2, h2, lo2); split2(v3, h3, lo3);
            *(unsigned*)(oh_ + off) = pack_bf2(h2, h3);
            *(unsigned*)(ol_ + off) = pack_bf2(lo2, lo3);
        }
    }
}

// ---------------- host orchestration ----------------
extern "C" void kernel_launch(void* const* d_in, const int* in_sizes, int n_in,
                              void* d_out, int out_size) {
    (void)in_sizes; (void)n_in; (void)out_size;

    const float* prefix = (const float*)d_in[0];
    const float* obs    = (const float*)d_in[2];
    const float* rdo    = (const float*)d_in[4];
    const float* ln1_s  = (const float*)d_in[6];
    const float* ln1_b  = (const float*)d_in[7];
    const float* wqkv   = (const float*)d_in[8];
    const float* bqkv   = (const float*)d_in[9];
    const float* wo     = (const float*)d_in[10];
    const float* bo     = (const float*)d_in[11];
    const float* ln2_s  = (const float*)d_in[12];
    const float* ln2_b  = (const float*)d_in[13];
    const float* w1     = (const float*)d_in[14];
    const float* b1     = (const float*)d_in[15];
    const float* w2     = (const float*)d_in[16];
    const float* b2     = (const float*)d_in[17];
    const float* lnf_s  = (const float*)d_in[18];
    const float* lnf_b  = (const float*)d_in[19];
    float* out = (float*)d_out;

    float* x;
    __nv_bfloat16 *yhi, *ylo, *qkvhi, *qkvlo, *atthi, *attlo, *ffnhi, *ffnlo;
    __nv_bfloat16 *wqkvT_hi, *wqkvT_lo, *woT_hi, *woT_lo, *w1T_hi, *w1T_lo, *w2T_hi, *w2T_lo;
    cudaGetSymbolAddress((void**)&x,     g_x);
    cudaGetSymbolAddress((void**)&yhi,   g_y_hi);
    cudaGetSymbolAddress((void**)&ylo,   g_y_lo);
    cudaGetSymbolAddress((void**)&qkvhi, g_qkv_hi);
    cudaGetSymbolAddress((void**)&qkvlo, g_qkv_lo);
    cudaGetSymbolAddress((void**)&atthi, g_att_hi);
    cudaGetSymbolAddress((void**)&attlo, g_att_lo);
    cudaGetSymbolAddress((void**)&ffnhi, g_ffn_hi);
    cudaGetSymbolAddress((void**)&ffnlo, g_ffn_lo);
    cudaGetSymbolAddress((void**)&wqkvT_hi, g_wqkvT_hi);
    cudaGetSymbolAddress((void**)&wqkvT_lo, g_wqkvT_lo);
    cudaGetSymbolAddress((void**)&woT_hi,   g_woT_hi);
    cudaGetSymbolAddress((void**)&woT_lo,   g_woT_lo);
    cudaGetSymbolAddress((void**)&w1T_hi,   g_w1T_hi);
    cudaGetSymbolAddress((void**)&w1T_lo,   g_w1T_lo);
    cudaGetSymbolAddress((void**)&w2T_hi,   g_w2T_hi);
    cudaGetSymbolAddress((void**)&w2T_lo,   g_w2T_lo);

    cudaFuncSetAttribute(wmma_gemm<0>, cudaFuncAttributeMaxDynamicSharedMemorySize, SMEM_GEMM);
    cudaFuncSetAttribute(wmma_gemm<1>, cudaFuncAttributeMaxDynamicSharedMemorySize, SMEM_GEMM);
    cudaFuncSetAttribute(wmma_gemm<2>, cudaFuncAttributeMaxDynamicSharedMemorySize, SMEM_GEMM);
    cudaFuncSetAttribute(attn_mma, cudaFuncAttributeMaxDynamicSharedMemorySize, ATTN_SMEM);

    assemble_kernel<<<2048, 256>>>(prefix, obs, rdo);

    const dim3 tb(32, 8);
    for (int l = 0; l < L_; l++) {
        wsplit_kernel<<<dim3(3 * D_ / 32, D_ / 32), tb>>>(
            wqkv + (size_t)l * D_ * 3 * D_,
            wqkvT_hi + (size_t)l * 3 * D_ * D_, wqkvT_lo + (size_t)l * 3 * D_ * D_, D_, 3 * D_);
        wsplit_kernel<<<dim3(D_ / 32, D_ / 32), tb>>>(
            wo + (size_t)l * D_ * D_,
            woT_hi + (size_t)l * D_ * D_, woT_lo + (size_t)l * D_ * D_, D_, D_);
        wsplit_kernel<<<dim3(F_ / 32, D_ / 32), tb>>>(
            w1 + (size_t)l * D_ * F_,
            w1T_hi + (size_t)l * F_ * D_, w1T_lo + (size_t)l * F_ * D_, D_, F_);
        wsplit_kernel<<<dim3(D_ / 32, F_ / 32), tb>>>(
            w2 + (size_t)l * F_ * D_,
            w2T_hi + (size_t)l * D_ * F_, w2T_lo + (size_t)l * D_ * F_, F_, D_);
    }

    const dim3 g_qkv_grid(3 * D_ / BN, M_ / BM);   // (18, 86)
    const dim3 g_wo_grid (D_ / BN,     M_ / BM);   // (6, 86)
    const dim3 g_w1_grid (F_ / BN,     M_ / BM);   // (24, 86)
    const dim3 g_attn((T_ + 63) / 64, NH_, B_);    // (22, 12, 8)

    for (int l = 0; l < L_; l++) {
        ln_split_kernel<<<M_, 256>>>(x, ln1_s + (size_t)l * D_, ln1_b + (size_t)l * D_, yhi, ylo);
        wmma_gemm<0><<<g_qkv_grid, 512, SMEM_GEMM>>>(
            yhi, ylo,
            wqkvT_hi + (size_t)l * 3 * D_ * D_, wqkvT_lo + (size_t)l * 3 * D_ * D_,
            bqkv + (size_t)l * 3 * D_, nullptr, nullptr, qkvhi, qkvlo, 3 * D_, D_);
        attn_mma<<<g_attn, 128, ATTN_SMEM>>>(qkvhi, qkvlo, atthi, attlo);
        wmma_gemm<2><<<g_wo_grid, 512, SMEM_GEMM>>>(
            atthi, attlo,
            woT_hi + (size_t)l * D_ * D_, woT_lo + (size_t)l * D_ * D_,
            bo + (size_t)l * D_, x, x, nullptr, nullptr, D_, D_);
        ln_split_kernel<<<M_, 256>>>(x, ln2_s + (size_t)l * D_, ln2_b + (size_t)l * D_, yhi, ylo);
        wmma_gemm<1><<<g_w1_grid, 512, SMEM_GEMM>>>(
            yhi, ylo,
            w1T_hi + (size_t)l * F_ * D_, w1T_lo + (size_t)l * F_ * D_,
            b1 + (size_t)l * F_, nullptr, nullptr, ffnhi, ffnlo, F_, D_);
        wmma_gemm<2><<<g_wo_grid, 512, SMEM_GEMM>>>(
            ffnhi, ffnlo,
            w2T_hi + (size_t)l * D_ * F_, w2T_lo + (size_t)l * D_ * F_,
            b2 + (size_t)l * D_, x, x, nullptr, nullptr, D_, F_);
    }

    ln_kernel<<<M_, 256>>>(x, lnf_s, lnf_b, out);
}

// round 7
// speedup vs baseline: 1.1457x; 1.1457x over previous
#include <cuda_runtime.h>
#include <cuda_bf16.h>
#include <math.h>
#include <stdint.h>

// ---------------- problem constants ----------------
namespace {
constexpr int B_  = 8;
constexpr int P_  = 16;
constexpr int HOR = 10;
constexpr int NO_ = 128;
constexpr int NR_ = 8;
constexpr int D_  = 768;
constexpr int NH_ = 12;
constexpr int HD_ = 64;
constexpr int F_  = 3072;
constexpr int L_  = 12;
constexpr int TPS = NO_ + NR_;          // 136
constexpr int T_  = P_ + HOR * TPS;     // 1376
constexpr int M_  = B_ * T_;            // 11008
constexpr float LN_EPS = 1e-6f;
constexpr float ATT_SCALE = 0.125f;     // 1/sqrt(64)

// GEMM tiling: 256 threads, 2x4 warp grid (64x32 warp tile), BK=64, cp.async 3-stage
constexpr int BM = 128;
constexpr int BN = 128;
constexpr int BK = 64;
constexpr int GRS = 72;                  // SMEM row stride in bf16 (144B), conflict-free ldmatrix
constexpr int TILE_B = 128 * GRS * 2;    // 18432 bytes per operand tile
constexpr int STAGE_B = 4 * TILE_B;      // Ahi,Alo,Bhi,Blo = 73728
constexpr int NSTAGE = 3;
constexpr int SMEM_GEMM = NSTAGE * STAGE_B;  // 221184

// attention smem layout (bf16 units unless noted)
constexpr int ARS   = 72;                // 144B row stride, conflict-free
constexpr int AT_QH = 0;
constexpr int AT_QL = 1 * 64 * ARS;
constexpr int AT_KH = 2 * 64 * ARS;
constexpr int AT_KL = 3 * 64 * ARS;
constexpr int AT_VH = 4 * 64 * ARS;
constexpr int AT_VL = 5 * 64 * ARS;
constexpr int AT_CODE_B = 6 * 64 * ARS * 2;     // byte offset of key codes
constexpr int ATTN_SMEM = AT_CODE_B + 64 * 4;   // 55552 bytes
}

// ---------------- scratch (device globals: no cudaMalloc allowed) ----------------
__device__ float g_x[(size_t)M_ * D_];
__device__ __nv_bfloat16 g_y_hi  [(size_t)M_ * D_];
__device__ __nv_bfloat16 g_y_lo  [(size_t)M_ * D_];
__device__ __nv_bfloat16 g_qkv_hi[(size_t)M_ * 3 * D_];
__device__ __nv_bfloat16 g_qkv_lo[(size_t)M_ * 3 * D_];
__device__ __nv_bfloat16 g_att_hi[(size_t)M_ * D_];
__device__ __nv_bfloat16 g_att_lo[(size_t)M_ * D_];
__device__ __nv_bfloat16 g_ffn_hi[(size_t)M_ * F_];
__device__ __nv_bfloat16 g_ffn_lo[(size_t)M_ * F_];
__device__ __nv_bfloat16 g_wqkvT_hi[(size_t)L_ * 3 * D_ * D_];
__device__ __nv_bfloat16 g_wqkvT_lo[(size_t)L_ * 3 * D_ * D_];
__device__ __nv_bfloat16 g_woT_hi  [(size_t)L_ * D_ * D_];
__device__ __nv_bfloat16 g_woT_lo  [(size_t)L_ * D_ * D_];
__device__ __nv_bfloat16 g_w1T_hi  [(size_t)L_ * F_ * D_];
__device__ __nv_bfloat16 g_w1T_lo  [(size_t)L_ * F_ * D_];
__device__ __nv_bfloat16 g_w2T_hi  [(size_t)L_ * D_ * F_];
__device__ __nv_bfloat16 g_w2T_lo  [(size_t)L_ * D_ * F_];

// ---------------- mma / async helpers ----------------
__device__ __forceinline__ unsigned smem_u32(const void* p) {
    return (unsigned)__cvta_generic_to_shared(p);
}
__device__ __forceinline__ void ldsm_x4(unsigned* r, unsigned addr) {
    asm volatile("ldmatrix.sync.aligned.m8n8.x4.shared.b16 {%0,%1,%2,%3}, [%4];"
                 : "=r"(r[0]), "=r"(r[1]), "=r"(r[2]), "=r"(r[3]) : "r"(addr));
}
__device__ __forceinline__ void ldsm_x4t(unsigned* r, unsigned addr) {
    asm volatile("ldmatrix.sync.aligned.m8n8.x4.trans.shared.b16 {%0,%1,%2,%3}, [%4];"
                 : "=r"(r[0]), "=r"(r[1]), "=r"(r[2]), "=r"(r[3]) : "r"(addr));
}
__device__ __forceinline__ void mma_bf16(float* c, const unsigned* a, const unsigned* b) {
    asm volatile(
        "mma.sync.aligned.m16n8k16.row.col.f32.bf16.bf16.f32 "
        "{%0,%1,%2,%3}, {%4,%5,%6,%7}, {%8,%9}, {%0,%1,%2,%3};"
        : "+f"(c[0]), "+f"(c[1]), "+f"(c[2]), "+f"(c[3])
        : "r"(a[0]), "r"(a[1]), "r"(a[2]), "r"(a[3]), "r"(b[0]), "r"(b[1]));
}
__device__ __forceinline__ void cp16(unsigned saddr, const void* g) {
    asm volatile("cp.async.cg.shared.global [%0], [%1], 16;" :: "r"(saddr), "l"(g));
}
__device__ __forceinline__ void cp_commit() {
    asm volatile("cp.async.commit_group;" ::: "memory");
}
template <int N>
__device__ __forceinline__ void cp_wait() {
    asm volatile("cp.async.wait_group %0;" :: "n"(N) : "memory");
}
__device__ __forceinline__ unsigned pack_bf2(__nv_bfloat16 a, __nv_bfloat16 b) {
    __nv_bfloat162 t(a, b);
    return *(unsigned*)&t;
}
__device__ __forceinline__ void split2(float v, __nv_bfloat16& h, __nv_bfloat16& l) {
    h = __float2bfloat16(v);
    l = __float2bfloat16(v - __bfloat162float(h));
}

// ---------------- misc helpers ----------------
__device__ __forceinline__ float gelu_tanh(float x) {
    float x3 = x * x * x;
    return 0.5f * x * (1.0f + tanhf(0.7978845608028654f * (x + 0.044715f * x3)));
}
__device__ __forceinline__ int tok_group(int i) {
    if (i < P_) return 0;
    return (((i - P_) % TPS) < NO_) ? 1 : 2;
}
__device__ __forceinline__ int tok_ts(int i) {
    return (i < P_) ? -1 : (i - P_) / TPS;
}
__device__ __forceinline__ bool allow_code(int gq, int tq, int kc) {
    int gk = kc & 3;
    int tk = kc >> 2;
    if (gk == 0) return true;
    if (gq == 0) return false;
    if (tk > tq) return false;
    return (gk == 1) || (gq == 2);
}

// ---------------- assemble ----------------
__global__ void assemble_kernel(const float* __restrict__ prefix,
                                const float* __restrict__ obs,
                                const float* __restrict__ rdo) {
    for (int idx = blockIdx.x * blockDim.x + threadIdx.x;
         idx < M_ * D_; idx += gridDim.x * blockDim.x) {
        int d = idx % D_;
        int bt = idx / D_;
        int t = bt % T_;
        int b = bt / T_;
        float v;
        if (t < P_) {
            v = prefix[((size_t)b * P_ + t) * D_ + d];
        } else {
            int tt = t - P_;
            int ho = tt / TPS;
            int r  = tt % TPS;
            if (r < NO_)
                v = obs[(((size_t)b * HOR + ho) * NO_ + r) * D_ + d];
            else
                v = rdo[(((size_t)b * HOR + ho) * NR_ + (r - NO_)) * D_ + d];
        }
        g_x[idx] = v;
    }
}

// ---------------- fused weight transpose + split (all 4 weights, all layers) ----------------
// grid = (6912, L_), block = (32, 8)
__global__ void wsplit_all_kernel(const float* __restrict__ wqkv, const float* __restrict__ wo,
                                  const float* __restrict__ w1, const float* __restrict__ w2,
                                  __nv_bfloat16* __restrict__ qh, __nv_bfloat16* __restrict__ ql,
                                  __nv_bfloat16* __restrict__ oh, __nv_bfloat16* __restrict__ ol,
                                  __nv_bfloat16* __restrict__ h1, __nv_bfloat16* __restrict__ l1,
                                  __nv_bfloat16* __restrict__ h2, __nv_bfloat16* __restrict__ l2) {
    __shared__ float t[32][33];
    const int l = blockIdx.y;
    int bx = blockIdx.x;
    const float* src;
    __nv_bfloat16 *hiT, *loT;
    int R, C;
    if (bx < 1728) {
        src = wqkv + (size_t)l * D_ * 3 * D_;
        hiT = qh + (size_t)l * 3 * D_ * D_;  loT = ql + (size_t)l * 3 * D_ * D_;
        R = D_; C = 3 * D_;
    } else if (bx < 2304) {
        bx -= 1728;
        src = wo + (size_t)l * D_ * D_;
        hiT = oh + (size_t)l * D_ * D_;  loT = ol + (size_t)l * D_ * D_;
        R = D_; C = D_;
    } else if (bx < 4608) {
        bx -= 2304;
        src = w1 + (size_t)l * D_ * F_;
        hiT = h1 + (size_t)l * F_ * D_;  loT = l1 + (size_t)l * F_ * D_;
        R = D_; C = F_;
    } else {
        bx -= 4608;
        src = w2 + (size_t)l * F_ * D_;
        hiT = h2 + (size_t)l * D_ * F_;  loT = l2 + (size_t)l * D_ * F_;
        R = F_; C = D_;
    }
    const int cols = C / 32;
    const int cb = (bx % cols) * 32, rb = (bx / cols) * 32;
    const int tx = threadIdx.x, ty = threadIdx.y;
    #pragma unroll
    for (int i = 0; i < 32; i += 8)
        t[ty + i][tx] = src[(size_t)(rb + ty + i) * C + cb + tx];
    __syncthreads();
    #pragma unroll
    for (int i = 0; i < 32; i += 8) {
        float v = t[tx][ty + i];
        __nv_bfloat16 h, lo;
        split2(v, h, lo);
        size_t o = (size_t)(cb + ty + i) * R + rb + tx;
        hiT[o] = h;
        loT[o] = lo;
    }
}

// ---------------- layernorm ----------------
__device__ __forceinline__ float block_reduce_sum(float v, float* red) {
    int lane = threadIdx.x & 31;
    int wid  = threadIdx.x >> 5;
    #pragma unroll
    for (int o = 16; o; o >>= 1) v += __shfl_down_sync(0xffffffffu, v, o);
    if (lane == 0) red[wid] = v;
    __syncthreads();
    if (threadIdx.x < 32) {
        float t = (threadIdx.x < 8) ? red[threadIdx.x] : 0.0f;
        #pragma unroll
        for (int o = 4; o; o >>= 1) t += __shfl_down_sync(0xffffffffu, t, o);
        if (threadIdx.x == 0) red[32] = t;
    }
    __syncthreads();
    return red[32];
}

__global__ void ln_kernel(const float* __restrict__ x,
                          const float* __restrict__ s,
                          const float* __restrict__ b,
                          float* __restrict__ y) {
    __shared__ float red[33];
    int row = blockIdx.x;
    const float* xp = x + (size_t)row * D_;
    float v0 = xp[threadIdx.x];
    float v1 = xp[threadIdx.x + 256];
    float v2 = xp[threadIdx.x + 512];
    float mu = block_reduce_sum(v0 + v1 + v2, red) * (1.0f / D_);
    float d0 = v0 - mu, d1 = v1 - mu, d2 = v2 - mu;
    float var = block_reduce_sum(d0 * d0 + d1 * d1 + d2 * d2, red) * (1.0f / D_);
    float inv = rsqrtf(var + LN_EPS);
    float* yp = y + (size_t)row * D_;
    yp[threadIdx.x      ] = d0 * inv * s[threadIdx.x      ] + b[threadIdx.x      ];
    yp[threadIdx.x + 256] = d1 * inv * s[threadIdx.x + 256] + b[threadIdx.x + 256];
    yp[threadIdx.x + 512] = d2 * inv * s[threadIdx.x + 512] + b[threadIdx.x + 512];
}

__global__ void ln_split_kernel(const float* __restrict__ x,
                                const float* __restrict__ s,
                                const float* __restrict__ b,
                                __nv_bfloat16* __restrict__ yhi,
                                __nv_bfloat16* __restrict__ ylo) {
    __shared__ float red[33];
    int row = blockIdx.x;
    const float* xp = x + (size_t)row * D_;
    float v0 = xp[threadIdx.x];
    float v1 = xp[threadIdx.x + 256];
    float v2 = xp[threadIdx.x + 512];
    float mu = block_reduce_sum(v0 + v1 + v2, red) * (1.0f / D_);
    float d0 = v0 - mu, d1 = v1 - mu, d2 = v2 - mu;
    float var = block_reduce_sum(d0 * d0 + d1 * d1 + d2 * d2, red) * (1.0f / D_);
    float inv = rsqrtf(var + LN_EPS);
    size_t base = (size_t)row * D_;
    #pragma unroll
    for (int i = 0; i < 3; i++) {
        int c = threadIdx.x + i * 256;
        float dv = (i == 0 ? d0 : (i == 1 ? d1 : d2));
        float v = dv * inv * s[c] + b[c];
        __nv_bfloat16 h, l;
        split2(v, h, l);
        yhi[base + c] = h;
        ylo[base + c] = l;
    }
}

// ---------------- split-bf16 warp-mma GEMM (BK=64, cp.async 3-stage, 1 barrier/iter) ----------------
// C[M,N] = (Ahi+Alo)[M,K] @ (Whi+Wlo)[N,K]^T + bias
// EPI 0: write split bf16 ; EPI 1: gelu -> split bf16 ; EPI 2: +R -> fp32
template <int EPI>
__global__ __launch_bounds__(256, 1) void wmma_gemm(
    const __nv_bfloat16* __restrict__ Ahi, const __nv_bfloat16* __restrict__ Alo,
    const __nv_bfloat16* __restrict__ Whi, const __nv_bfloat16* __restrict__ Wlo,
    const float* __restrict__ bias, const float* __restrict__ R,
    float* __restrict__ C,
    __nv_bfloat16* __restrict__ Chi, __nv_bfloat16* __restrict__ Clo,
    int Ndim, int Kdim) {
    extern __shared__ char smem[];
    const unsigned sbase = smem_u32(smem);
    const int tid = threadIdx.x;
    const int lane = tid & 31;
    const int wid = tid >> 5;
    const int warp_m = wid & 1;          // 2 warp rows (64 M each)
    const int warp_n = wid >> 1;         // 4 warp cols (32 N each)
    const int bm = blockIdx.y * BM;
    const int bn = blockIdx.x * BN;
    const int NK = Kdim / BK;

    auto issue_stage = [&](int st) {
        const unsigned sb = sbase + (unsigned)((st % NSTAGE) * STAGE_B);
        const int k0 = st * BK;
        #pragma unroll
        for (int i = 0; i < 4; i++) {
            int f = tid + i * 256;
            int r = f >> 3, cc = f & 7;
            unsigned so = (unsigned)(r * (GRS * 2) + cc * 16);
            size_t ao = (size_t)(bm + r) * Kdim + k0 + 8 * cc;
            size_t bo = (size_t)(bn + r) * Kdim + k0 + 8 * cc;
            cp16(sb + so,              Ahi + ao);
            cp16(sb + TILE_B + so,     Alo + ao);
            cp16(sb + 2 * TILE_B + so, Whi + bo);
            cp16(sb + 3 * TILE_B + so, Wlo + bo);
        }
        cp_commit();
    };

    const unsigned a_base = (unsigned)((warp_m * 64 + (lane & 15)) * (GRS * 2) + (lane >> 4) * 16);
    const unsigned b_row = (unsigned)(warp_n * 32 + (lane & 7) + ((lane >> 4) << 3));
    const unsigned b_base = (unsigned)(b_row * (GRS * 2) + (((lane >> 3) & 1) * 16));

    float acc[4][4][4];
    #pragma unroll
    for (int mt = 0; mt < 4; mt++)
        #pragma unroll
        for (int nt = 0; nt < 4; nt++)
            #pragma unroll
            for (int r = 0; r < 4; r++) acc[mt][nt][r] = 0.0f;

    issue_stage(0);
    if (NK > 1) issue_stage(1);

    for (int i = 0; i < NK; i++) {
        if (i + 1 < NK) cp_wait<1>(); else cp_wait<0>();
        __syncthreads();
        if (i + 2 < NK) issue_stage(i + 2);

        const unsigned tAhi = sbase + (unsigned)((i % NSTAGE) * STAGE_B);
        const unsigned tAlo = tAhi + TILE_B;
        const unsigned tBhi = tAlo + TILE_B;
        const unsigned tBlo = tBhi + TILE_B;

        #pragma unroll
        for (int ks = 0; ks < 4; ks++) {
            unsigned fah[4][4], fal[4][4];
            unsigned fbh[2][4], fbl[2][4];
            #pragma unroll
            for (int mt = 0; mt < 4; mt++) {
                unsigned ao = a_base + (unsigned)(mt * 16 * (GRS * 2) + ks * 32);
                ldsm_x4(fah[mt], tAhi + ao);
                ldsm_x4(fal[mt], tAlo + ao);
            }
            #pragma unroll
            for (int pr = 0; pr < 2; pr++) {
                unsigned bo = b_base + (unsigned)(pr * 16 * (GRS * 2) + ks * 32);
                ldsm_x4(fbh[pr], tBhi + bo);
                ldsm_x4(fbl[pr], tBlo + bo);
            }
            #pragma unroll
            for (int mt = 0; mt < 4; mt++) {
                #pragma unroll
                for (int nt = 0; nt < 4; nt++) {
                    const unsigned* bH = &fbh[nt >> 1][(nt & 1) * 2];
                    const unsigned* bL = &fbl[nt >> 1][(nt & 1) * 2];
                    mma_bf16(acc[mt][nt], fah[mt], bH);
                    mma_bf16(acc[mt][nt], fah[mt], bL);
                    mma_bf16(acc[mt][nt], fal[mt], bH);
                }
            }
        }
    }

    // ---- epilogue ----
    const int g = lane >> 2, tg = lane & 3;
    #pragma unroll
    for (int mt = 0; mt < 4; mt++) {
        #pragma unroll
        for (int nt = 0; nt < 4; nt++) {
            int row0 = bm + warp_m * 64 + mt * 16 + g;
            int col  = bn + warp_n * 32 + nt * 8 + tg * 2;
            float2 bv = *(const float2*)(bias + col);
            float c0 = acc[mt][nt][0] + bv.x;
            float c1 = acc[mt][nt][1] + bv.y;
            float c2 = acc[mt][nt][2] + bv.x;
            float c3 = acc[mt][nt][3] + bv.y;
            size_t o0 = (size_t)row0 * Ndim + col;
            size_t o1 = o0 + (size_t)8 * Ndim;
            if (EPI == 2) {
                float2 r0 = *(const float2*)(R + o0);
                float2 r1 = *(const float2*)(R + o1);
                c0 += r0.x; c1 += r0.y; c2 += r1.x; c3 += r1.y;
                *(float2*)(C + o0) = make_float2(c0, c1);
                *(float2*)(C + o1) = make_float2(c2, c3);
            } else {
                if (EPI == 1) {
                    c0 = gelu_tanh(c0); c1 = gelu_tanh(c1);
                    c2 = gelu_tanh(c2); c3 = gelu_tanh(c3);
                }
                __nv_bfloat16 h0, l0v, h1, l1v, h2, l2v, h3, l3v;
                split2(c0, h0, l0v); split2(c1, h1, l1v);
                split2(c2, h2, l2v); split2(c3, h3, l3v);
                *(unsigned*)(Chi + o0) = pack_bf2(h0, h1);
                *(unsigned*)(Clo + o0) = pack_bf2(l0v, l1v);
                *(unsigned*)(Chi + o1) = pack_bf2(h2, h3);
                *(unsigned*)(Clo + o1) = pack_bf2(l2v, l3v);
            }
        }
    }
}

// ---------------- tensor-core flash attention (split bf16, R4 form) ----------------
__global__ __launch_bounds__(128) void attn_mma(
    const __nv_bfloat16* __restrict__ qh_, const __nv_bfloat16* __restrict__ ql_,
    __nv_bfloat16* __restrict__ oh_, __nv_bfloat16* __restrict__ ol_) {
    extern __shared__ char smem[];
    __nv_bfloat16* sb = (__nv_bfloat16*)smem;
    int* kcode = (int*)(smem + AT_CODE_B);
    const unsigned sbase = smem_u32(smem);
    const int h = blockIdx.y, b = blockIdx.z;
    const int q0 = blockIdx.x * 64;
    const int tid = threadIdx.x;
    const int lane = tid & 31;
    const int warp = tid >> 5;
    const int tg2 = (lane & 3) * 2;

    for (int idx = tid; idx < 64 * 8; idx += 128) {
        int r = idx >> 3, c = idx & 7;
        int gr = min(q0 + r, T_ - 1);
        size_t src = ((size_t)(b * T_ + gr)) * (3 * D_) + h * HD_ + c * 8;
        *(uint4*)&sb[AT_QH + r * ARS + c * 8] = *(const uint4*)(qh_ + src);
        *(uint4*)&sb[AT_QL + r * ARS + c * 8] = *(const uint4*)(ql_ + src);
    }
    __syncthreads();

    unsigned qfh[4][4], qfl[4][4];
    {
        unsigned rowoff = (unsigned)((warp * 16 + (lane & 15)) * (ARS * 2)) + (lane >> 4) * 16;
        #pragma unroll
        for (int ks = 0; ks < 4; ks++) {
            ldsm_x4(qfh[ks], sbase + AT_QH * 2 + rowoff + ks * 32);
            ldsm_x4(qfl[ks], sbase + AT_QL * 2 + rowoff + ks * 32);
        }
    }

    const int r0 = q0 + warp * 16 + (lane >> 2);
    const int r1 = r0 + 8;
    const int rc0 = min(r0, T_ - 1), rc1 = min(r1, T_ - 1);
    const int gq0 = tok_group(rc0), tq0 = tok_ts(rc0);
    const int gq1 = tok_group(rc1), tq1 = tok_ts(rc1);

    float m0 = -1e30f, m1 = -1e30f, l0 = 0.0f, l1 = 0.0f;
    float o[8][4];
    #pragma unroll
    for (int nt = 0; nt < 8; nt++)
        #pragma unroll
        for (int r = 0; r < 4; r++) o[nt][r] = 0.0f;

    const int rlast = min(q0 + 63, T_ - 1);
    const int kmax = P_ + (tok_ts(rlast) + 1) * TPS;

    const unsigned kb = (unsigned)(((lane & 7) + ((lane >> 4) << 3)) * (ARS * 2)) +
                        ((lane >> 3) & 1) * 16;

    for (int k0 = 0; k0 < kmax; k0 += 64) {
        __syncthreads();
        for (int idx = tid; idx < 64 * 8; idx += 128) {
            int r = idx >> 3, c = idx & 7;
            int kr = k0 + r;
            uint4 z = make_uint4(0, 0, 0, 0);
            uint4 kvh = z, kvl = z, vvh = z, vvl = z;
            if (kr < T_) {
                size_t src = ((size_t)(b * T_ + kr)) * (3 * D_) + D_ + h * HD_ + c * 8;
                kvh = *(const uint4*)(qh_ + src);
                kvl = *(const uint4*)(ql_ + src);
                vvh = *(const uint4*)(qh_ + src + D_);
                vvl = *(const uint4*)(ql_ + src + D_);
            }
            *(uint4*)&sb[AT_KH + r * ARS + c * 8] = kvh;
            *(uint4*)&sb[AT_KL + r * ARS + c * 8] = kvl;
            *(uint4*)&sb[AT_VH + r * ARS + c * 8] = vvh;
            *(uint4*)&sb[AT_VL + r * ARS + c * 8] = vvl;
        }
        if (tid < 64) {
            int kg = k0 + tid;
            kcode[tid] = (kg < kmax && kg < T_)
                       ? ((tok_ts(kg) << 2) | tok_group(kg))
                       : ((0x3FFF << 2) | 3);
        }
        __syncthreads();

        float s[8][4];
        #pragma unroll
        for (int nt = 0; nt < 8; nt++)
            #pragma unroll
            for (int r = 0; r < 4; r++) s[nt][r] = 0.0f;

        #pragma unroll
        for (int kg = 0; kg < 4; kg++) {
            #pragma unroll
            for (int ks = 0; ks < 4; ks++) {
                unsigned kh[4], kl[4];
                unsigned addr = sbase + kb + (unsigned)(kg * 16 * (ARS * 2)) + ks * 32;
                ldsm_x4(kh, addr + AT_KH * 2);
                ldsm_x4(kl, addr + AT_KL * 2);
                #pragma unroll
                for (int half = 0; half < 2; half++) {
                    int nt = kg * 2 + half;
                    mma_bf16(s[nt], qfh[ks], &kh[half * 2]);
                    mma_bf16(s[nt], qfh[ks], &kl[half * 2]);
                    mma_bf16(s[nt], qfl[ks], &kh[half * 2]);
                }
            }
        }

        #pragma unroll
        for (int nt = 0; nt < 8; nt++) {
            int kc0 = kcode[nt * 8 + tg2];
            int kc1 = kcode[nt * 8 + tg2 + 1];
            s[nt][0] = allow_code(gq0, tq0, kc0) ? s[nt][0] * ATT_SCALE : -1e30f;
            s[nt][1] = allow_code(gq0, tq0, kc1) ? s[nt][1] * ATT_SCALE : -1e30f;
            s[nt][2] = allow_code(gq1, tq1, kc0) ? s[nt][2] * ATT_SCALE : -1e30f;
            s[nt][3] = allow_code(gq1, tq1, kc1) ? s[nt][3] * ATT_SCALE : -1e30f;
        }

        float mx0 = -1e30f, mx1 = -1e30f;
        #pragma unroll
        for (int nt = 0; nt < 8; nt++) {
            mx0 = fmaxf(mx0, fmaxf(s[nt][0], s[nt][1]));
            mx1 = fmaxf(mx1, fmaxf(s[nt][2], s[nt][3]));
        }
        mx0 = fmaxf(mx0, __shfl_xor_sync(0xffffffffu, mx0, 1));
        mx0 = fmaxf(mx0, __shfl_xor_sync(0xffffffffu, mx0, 2));
        mx1 = fmaxf(mx1, __shfl_xor_sync(0xffffffffu, mx1, 1));
        mx1 = fmaxf(mx1, __shfl_xor_sync(0xffffffffu, mx1, 2));
        float mn0 = fmaxf(m0, mx0), mn1 = fmaxf(m1, mx1);
        float corr0 = __expf(m0 - mn0), corr1 = __expf(m1 - mn1);
        m0 = mn0; m1 = mn1;
        l0 *= corr0; l1 *= corr1;
        #pragma unroll
        for (int nt = 0; nt < 8; nt++) {
            o[nt][0] *= corr0; o[nt][1] *= corr0;
            o[nt][2] *= corr1; o[nt][3] *= corr1;
        }

        #pragma unroll
        for (int kv = 0; kv < 4; kv++) {
            unsigned ph[4], pl[4];
            #pragma unroll
            for (int half = 0; half < 2; half++) {
                int nt = kv * 2 + half;
                float p0 = __expf(s[nt][0] - m0);
                float p1 = __expf(s[nt][1] - m0);
                float p2 = __expf(s[nt][2] - m1);
                float p3 = __expf(s[nt][3] - m1);
                l0 += p0 + p1;
                l1 += p2 + p3;
                __nv_bfloat16 h0, lo0, h1, lo1, h2, lo2, h3, lo3;
                split2(p0, h0, lo0); split2(p1, h1, lo1);
                split2(p2, h2, lo2); split2(p3, h3, lo3);
                ph[half * 2 + 0] = pack_bf2(h0, h1);
                ph[half * 2 + 1] = pack_bf2(h2, h3);
                pl[half * 2 + 0] = pack_bf2(lo0, lo1);
                pl[half * 2 + 1] = pack_bf2(lo2, lo3);
            }
            #pragma unroll
            for (int dg = 0; dg < 4; dg++) {
                unsigned vh[4], vl[4];
                unsigned addr = sbase + kb + (unsigned)(kv * 16 * (ARS * 2)) + dg * 32;
                ldsm_x4t(vh, addr + AT_VH * 2);
                ldsm_x4t(vl, addr + AT_VL * 2);
                #pragma unroll
                for (int half = 0; half < 2; half++) {
                    int nt = dg * 2 + half;
                    unsigned bhp[2] = {vh[half], vh[2 + half]};
                    unsigned blp[2] = {vl[half], vl[2 + half]};
                    mma_bf16(o[nt], ph, bhp);
                    mma_bf16(o[nt], ph, blp);
                    mma_bf16(o[nt], pl, bhp);
                }
            }
        }
    }

    l0 += __shfl_xor_sync(0xffffffffu, l0, 1);
    l0 += __shfl_xor_sync(0xffffffffu, l0, 2);
    l1 += __shfl_xor_sync(0xffffffffu, l1, 1);
    l1 += __shfl_xor_sync(0xffffffffu, l1, 2);
    float li0 = 1.0f / l0, li1 = 1.0f / l1;

    #pragma unroll
    for (int nt = 0; nt < 8; nt++) {
        int d = h * HD_ + nt * 8 + tg2;
        if (r0 < T_) {
            size_t off = ((size_t)(b * T_ + r0)) * D_ + d;
            float v0 = o[nt][0] * li0, v1 = o[nt][1] * li0;
            __nv_bfloat16 h0, lo0, h1, lo1;
            split2(v0, h0, lo0); split2(v1, h1, lo1);
            *(unsigned*)(oh_ + off) = pack_bf2(h0, h1);
            *(unsigned*)(ol_ + off) = pack_bf2(lo0, lo1);
        }
        if (r1 < T_) {
            size_t off = ((size_t)(b * T_ + r1)) * D_ + d;
            float v2 = o[nt][2] * li1, v3 = o[nt][3] * li1;
            __nv_bfloat16 h2, lo2, h3, lo3;
            split2(v2, h2, lo2); split2(v3, h3, lo3);
            *(unsigned*)(oh_ + off) = pack_bf2(h2, h3);
            *(unsigned*)(ol_ + off) = pack_bf2(lo2, lo3);
        }
    }
}

// ---------------- host orchestration ----------------
extern "C" void kernel_launch(void* const* d_in, const int* in_sizes, int n_in,
                              void* d_out, int out_size) {
    (void)in_sizes; (void)n_in; (void)out_size;

    const float* prefix = (const float*)d_in[0];
    const float* obs    = (const float*)d_in[2];
    const float* rdo    = (const float*)d_in[4];
    const float* ln1_s  = (const float*)d_in[6];
    const float* ln1_b  = (const float*)d_in[7];
    const float* wqkv   = (const float*)d_in[8];
    const float* bqkv   = (const float*)d_in[9];
    const float* wo     = (const float*)d_in[10];
    const float* bo     = (const float*)d_in[11];
    const float* ln2_s  = (const float*)d_in[12];
    const float* ln2_b  = (const float*)d_in[13];
    const float* w1     = (const float*)d_in[14];
    const float* b1     = (const float*)d_in[15];
    const float* w2     = (const float*)d_in[16];
    const float* b2     = (const float*)d_in[17];
    const float* lnf_s  = (const float*)d_in[18];
    const float* lnf_b  = (const float*)d_in[19];
    float* out = (float*)d_out;

    float* x;
    __nv_bfloat16 *yhi, *ylo, *qkvhi, *qkvlo, *atthi, *attlo, *ffnhi, *ffnlo;
    __nv_bfloat16 *wqkvT_hi, *wqkvT_lo, *woT_hi, *woT_lo, *w1T_hi, *w1T_lo, *w2T_hi, *w2T_lo;
    cudaGetSymbolAddress((void**)&x,     g_x);
    cudaGetSymbolAddress((void**)&yhi,   g_y_hi);
    cudaGetSymbolAddress((void**)&ylo,   g_y_lo);
    cudaGetSymbolAddress((void**)&qkvhi, g_qkv_hi);
    cudaGetSymbolAddress((void**)&qkvlo, g_qkv_lo);
    cudaGetSymbolAddress((void**)&atthi, g_att_hi);
    cudaGetSymbolAddress((void**)&attlo, g_att_lo);
    cudaGetSymbolAddress((void**)&ffnhi, g_ffn_hi);
    cudaGetSymbolAddress((void**)&ffnlo, g_ffn_lo);
    cudaGetSymbolAddress((void**)&wqkvT_hi, g_wqkvT_hi);
    cudaGetSymbolAddress((void**)&wqkvT_lo, g_wqkvT_lo);
    cudaGetSymbolAddress((void**)&woT_hi,   g_woT_hi);
    cudaGetSymbolAddress((void**)&woT_lo,   g_woT_lo);
    cudaGetSymbolAddress((void**)&w1T_hi,   g_w1T_hi);
    cudaGetSymbolAddress((void**)&w1T_lo,   g_w1T_lo);
    cudaGetSymbolAddress((void**)&w2T_hi,   g_w2T_hi);
    cudaGetSymbolAddress((void**)&w2T_lo,   g_w2T_lo);

    cudaFuncSetAttribute(wmma_gemm<0>, cudaFuncAttributeMaxDynamicSharedMemorySize, SMEM_GEMM);
    cudaFuncSetAttribute(wmma_gemm<1>, cudaFuncAttributeMaxDynamicSharedMemorySize, SMEM_GEMM);
    cudaFuncSetAttribute(wmma_gemm<2>, cudaFuncAttributeMaxDynamicSharedMemorySize, SMEM_GEMM);
    cudaFuncSetAttribute(attn_mma, cudaFuncAttributeMaxDynamicSharedMemorySize, ATTN_SMEM);

    assemble_kernel<<<2048, 256>>>(prefix, obs, rdo);

    wsplit_all_kernel<<<dim3(6912, L_), dim3(32, 8)>>>(
        wqkv, wo, w1, w2,
        wqkvT_hi, wqkvT_lo, woT_hi, woT_lo, w1T_hi, w1T_lo, w2T_hi, w2T_lo);

    const dim3 g_qkv_grid(3 * D_ / BN, M_ / BM);   // (18, 86)
    const dim3 g_wo_grid (D_ / BN,     M_ / BM);   // (6, 86)
    const dim3 g_w1_grid (F_ / BN,     M_ / BM);   // (24, 86)
    const dim3 g_attn((T_ + 63) / 64, NH_, B_);    // (22, 12, 8)

    for (int l = 0; l < L_; l++) {
        ln_split_kernel<<<M_, 256>>>(x, ln1_s + (size_t)l * D_, ln1_b + (size_t)l * D_, yhi, ylo);
        wmma_gemm<0><<<g_qkv_grid, 256, SMEM_GEMM>>>(
            yhi, ylo,
            wqkvT_hi + (size_t)l * 3 * D_ * D_, wqkvT_lo + (size_t)l * 3 * D_ * D_,
            bqkv + (size_t)l * 3 * D_, nullptr, nullptr, qkvhi, qkvlo, 3 * D_, D_);
        attn_mma<<<g_attn, 128, ATTN_SMEM>>>(qkvhi, qkvlo, atthi, attlo);
        wmma_gemm<2><<<g_wo_grid, 256, SMEM_GEMM>>>(
            atthi, attlo,
            woT_hi + (size_t)l * D_ * D_, woT_lo + (size_t)l * D_ * D_,
            bo + (size_t)l * D_, x, x, nullptr, nullptr, D_, D_);
        ln_split_kernel<<<M_, 256>>>(x, ln2_s + (size_t)l * D_, ln2_b + (size_t)l * D_, yhi, ylo);
        wmma_gemm<1><<<g_w1_grid, 256, SMEM_GEMM>>>(
            yhi, ylo,
            w1T_hi + (size_t)l * F_ * D_, w1T_lo + (size_t)l * F_ * D_,
            b1 + (size_t)l * F_, nullptr, nullptr, ffnhi, ffnlo, F_, D_);
        wmma_gemm<2><<<g_wo_grid, 256, SMEM_GEMM>>>(
            ffnhi, ffnlo,
            w2T_hi + (size_t)l * D_ * F_, w2T_lo + (size_t)l * D_ * F_,
            b2 + (size_t)l * D_, x, x, nullptr, nullptr, D_, F_);
    }

    ln_kernel<<<M_, 256>>>(x, lnf_s, lnf_b, out);
}

// round 8
// speedup vs baseline: 1.1670x; 1.0186x over previous
#include <cuda_runtime.h>
#include <cuda_bf16.h>
#include <math.h>
#include <stdint.h>

// ---------------- problem constants ----------------
namespace {
constexpr int B_  = 8;
constexpr int P_  = 16;
constexpr int HOR = 10;
constexpr int NO_ = 128;
constexpr int NR_ = 8;
constexpr int D_  = 768;
constexpr int NH_ = 12;
constexpr int HD_ = 64;
constexpr int F_  = 3072;
constexpr int L_  = 12;
constexpr int TPS = NO_ + NR_;          // 136
constexpr int T_  = P_ + HOR * TPS;     // 1376
constexpr int M_  = B_ * T_;            // 11008
constexpr float LN_EPS = 1e-6f;
constexpr float ATT_SCALE = 0.125f;     // 1/sqrt(64)

// GEMM tiling: 256 threads, 2x4 warp grid (64x32 warp tile), BK=32, 2-stage cp.async,
// sized for 2 CTAs/SM (smem 80KB/CTA, <=128 regs via launch_bounds)
constexpr int BM = 128;
constexpr int BN = 128;
constexpr int BK = 32;
constexpr int RS = 40;                   // SMEM row stride in bf16 (80B), conflict-free ldmatrix
constexpr int TILE_B = 128 * RS * 2;     // 10240 bytes per operand tile
constexpr int STAGE_B = 4 * TILE_B;      // Ahi,Alo,Bhi,Blo = 40960
constexpr int NSTAGE = 2;
constexpr int SMEM_GEMM = NSTAGE * STAGE_B;  // 81920

// attention smem layout (bf16 units unless noted)
constexpr int ARS   = 72;                // 144B row stride, conflict-free
constexpr int AT_QH = 0;
constexpr int AT_QL = 1 * 64 * ARS;
constexpr int AT_KH = 2 * 64 * ARS;
constexpr int AT_KL = 3 * 64 * ARS;
constexpr int AT_VH = 4 * 64 * ARS;
constexpr int AT_VL = 5 * 64 * ARS;
constexpr int AT_CODE_B = 6 * 64 * ARS * 2;     // byte offset of key codes
constexpr int ATTN_SMEM = AT_CODE_B + 64 * 4;   // 55552 bytes
}

// ---------------- scratch (device globals: no cudaMalloc allowed) ----------------
__device__ float g_x[(size_t)M_ * D_];
__device__ __nv_bfloat16 g_y_hi  [(size_t)M_ * D_];
__device__ __nv_bfloat16 g_y_lo  [(size_t)M_ * D_];
__device__ __nv_bfloat16 g_qkv_hi[(size_t)M_ * 3 * D_];
__device__ __nv_bfloat16 g_qkv_lo[(size_t)M_ * 3 * D_];
__device__ __nv_bfloat16 g_att_hi[(size_t)M_ * D_];
__device__ __nv_bfloat16 g_att_lo[(size_t)M_ * D_];
__device__ __nv_bfloat16 g_ffn_hi[(size_t)M_ * F_];
__device__ __nv_bfloat16 g_ffn_lo[(size_t)M_ * F_];
__device__ __nv_bfloat16 g_wqkvT_hi[(size_t)L_ * 3 * D_ * D_];
__device__ __nv_bfloat16 g_wqkvT_lo[(size_t)L_ * 3 * D_ * D_];
__device__ __nv_bfloat16 g_woT_hi  [(size_t)L_ * D_ * D_];
__device__ __nv_bfloat16 g_woT_lo  [(size_t)L_ * D_ * D_];
__device__ __nv_bfloat16 g_w1T_hi  [(size_t)L_ * F_ * D_];
__device__ __nv_bfloat16 g_w1T_lo  [(size_t)L_ * F_ * D_];
__device__ __nv_bfloat16 g_w2T_hi  [(size_t)L_ * D_ * F_];
__device__ __nv_bfloat16 g_w2T_lo  [(size_t)L_ * D_ * F_];

// ---------------- mma / async helpers ----------------
__device__ __forceinline__ unsigned smem_u32(const void* p) {
    return (unsigned)__cvta_generic_to_shared(p);
}
__device__ __forceinline__ void ldsm_x4(unsigned* r, unsigned addr) {
    asm volatile("ldmatrix.sync.aligned.m8n8.x4.shared.b16 {%0,%1,%2,%3}, [%4];"
                 : "=r"(r[0]), "=r"(r[1]), "=r"(r[2]), "=r"(r[3]) : "r"(addr));
}
__device__ __forceinline__ void ldsm_x4t(unsigned* r, unsigned addr) {
    asm volatile("ldmatrix.sync.aligned.m8n8.x4.trans.shared.b16 {%0,%1,%2,%3}, [%4];"
                 : "=r"(r[0]), "=r"(r[1]), "=r"(r[2]), "=r"(r[3]) : "r"(addr));
}
__device__ __forceinline__ void mma_bf16(float* c, const unsigned* a, const unsigned* b) {
    asm volatile(
        "mma.sync.aligned.m16n8k16.row.col.f32.bf16.bf16.f32 "
        "{%0,%1,%2,%3}, {%4,%5,%6,%7}, {%8,%9}, {%0,%1,%2,%3};"
        : "+f"(c[0]), "+f"(c[1]), "+f"(c[2]), "+f"(c[3])
        : "r"(a[0]), "r"(a[1]), "r"(a[2]), "r"(a[3]), "r"(b[0]), "r"(b[1]));
}
__device__ __forceinline__ void cp16(unsigned saddr, const void* g) {
    asm volatile("cp.async.cg.shared.global [%0], [%1], 16;" :: "r"(saddr), "l"(g));
}
__device__ __forceinline__ void cp_commit() {
    asm volatile("cp.async.commit_group;" ::: "memory");
}
template <int N>
__device__ __forceinline__ void cp_wait() {
    asm volatile("cp.async.wait_group %0;" :: "n"(N) : "memory");
}
__device__ __forceinline__ unsigned pack_bf2(__nv_bfloat16 a, __nv_bfloat16 b) {
    __nv_bfloat162 t(a, b);
    return *(unsigned*)&t;
}
__device__ __forceinline__ void split2(float v, __nv_bfloat16& h, __nv_bfloat16& l) {
    h = __float2bfloat16(v);
    l = __float2bfloat16(v - __bfloat162float(h));
}

// ---------------- misc helpers ----------------
__device__ __forceinline__ float gelu_tanh(float x) {
    float x3 = x * x * x;
    return 0.5f * x * (1.0f + tanhf(0.7978845608028654f * (x + 0.044715f * x3)));
}
__device__ __forceinline__ int tok_group(int i) {
    if (i < P_) return 0;
    return (((i - P_) % TPS) < NO_) ? 1 : 2;
}
__device__ __forceinline__ int tok_ts(int i) {
    return (i < P_) ? -1 : (i - P_) / TPS;
}
__device__ __forceinline__ bool allow_code(int gq, int tq, int kc) {
    int gk = kc & 3;
    int tk = kc >> 2;
    if (gk == 0) return true;
    if (gq == 0) return false;
    if (tk > tq) return false;
    return (gk == 1) || (gq == 2);
}

// ---------------- assemble ----------------
__global__ void assemble_kernel(const float* __restrict__ prefix,
                                const float* __restrict__ obs,
                                const float* __restrict__ rdo) {
    for (int idx = blockIdx.x * blockDim.x + threadIdx.x;
         idx < M_ * D_; idx += gridDim.x * blockDim.x) {
        int d = idx % D_;
        int bt = idx / D_;
        int t = bt % T_;
        int b = bt / T_;
        float v;
        if (t < P_) {
            v = prefix[((size_t)b * P_ + t) * D_ + d];
        } else {
            int tt = t - P_;
            int ho = tt / TPS;
            int r  = tt % TPS;
            if (r < NO_)
                v = obs[(((size_t)b * HOR + ho) * NO_ + r) * D_ + d];
            else
                v = rdo[(((size_t)b * HOR + ho) * NR_ + (r - NO_)) * D_ + d];
        }
        g_x[idx] = v;
    }
}

// ---------------- fused weight transpose + split (all 4 weights, all layers) ----------------
__global__ void wsplit_all_kernel(const float* __restrict__ wqkv, const float* __restrict__ wo,
                                  const float* __restrict__ w1, const float* __restrict__ w2,
                                  __nv_bfloat16* __restrict__ qh, __nv_bfloat16* __restrict__ ql,
                                  __nv_bfloat16* __restrict__ oh, __nv_bfloat16* __restrict__ ol,
                                  __nv_bfloat16* __restrict__ h1, __nv_bfloat16* __restrict__ l1,
                                  __nv_bfloat16* __restrict__ h2, __nv_bfloat16* __restrict__ l2) {
    __shared__ float t[32][33];
    const int l = blockIdx.y;
    int bx = blockIdx.x;
    const float* src;
    __nv_bfloat16 *hiT, *loT;
    int R, C;
    if (bx < 1728) {
        src = wqkv + (size_t)l * D_ * 3 * D_;
        hiT = qh + (size_t)l * 3 * D_ * D_;  loT = ql + (size_t)l * 3 * D_ * D_;
        R = D_; C = 3 * D_;
    } else if (bx < 2304) {
        bx -= 1728;
        src = wo + (size_t)l * D_ * D_;
        hiT = oh + (size_t)l * D_ * D_;  loT = ol + (size_t)l * D_ * D_;
        R = D_; C = D_;
    } else if (bx < 4608) {
        bx -= 2304;
        src = w1 + (size_t)l * D_ * F_;
        hiT = h1 + (size_t)l * F_ * D_;  loT = l1 + (size_t)l * F_ * D_;
        R = D_; C = F_;
    } else {
        bx -= 4608;
        src = w2 + (size_t)l * F_ * D_;
        hiT = h2 + (size_t)l * D_ * F_;  loT = l2 + (size_t)l * D_ * F_;
        R = F_; C = D_;
    }
    const int cols = C / 32;
    const int cb = (bx % cols) * 32, rb = (bx / cols) * 32;
    const int tx = threadIdx.x, ty = threadIdx.y;
    #pragma unroll
    for (int i = 0; i < 32; i += 8)
        t[ty + i][tx] = src[(size_t)(rb + ty + i) * C + cb + tx];
    __syncthreads();
    #pragma unroll
    for (int i = 0; i < 32; i += 8) {
        float v = t[tx][ty + i];
        __nv_bfloat16 h, lo;
        split2(v, h, lo);
        size_t o = (size_t)(cb + ty + i) * R + rb + tx;
        hiT[o] = h;
        loT[o] = lo;
    }
}

// ---------------- layernorm ----------------
__device__ __forceinline__ float block_reduce_sum(float v, float* red) {
    int lane = threadIdx.x & 31;
    int wid  = threadIdx.x >> 5;
    #pragma unroll
    for (int o = 16; o; o >>= 1) v += __shfl_down_sync(0xffffffffu, v, o);
    if (lane == 0) red[wid] = v;
    __syncthreads();
    if (threadIdx.x < 32) {
        float t = (threadIdx.x < 8) ? red[threadIdx.x] : 0.0f;
        #pragma unroll
        for (int o = 4; o; o >>= 1) t += __shfl_down_sync(0xffffffffu, t, o);
        if (threadIdx.x == 0) red[32] = t;
    }
    __syncthreads();
    return red[32];
}

__global__ void ln_kernel(const float* __restrict__ x,
                          const float* __restrict__ s,
                          const float* __restrict__ b,
                          float* __restrict__ y) {
    __shared__ float red[33];
    int row = blockIdx.x;
    const float* xp = x + (size_t)row * D_;
    float v0 = xp[threadIdx.x];
    float v1 = xp[threadIdx.x + 256];
    float v2 = xp[threadIdx.x + 512];
    float mu = block_reduce_sum(v0 + v1 + v2, red) * (1.0f / D_);
    float d0 = v0 - mu, d1 = v1 - mu, d2 = v2 - mu;
    float var = block_reduce_sum(d0 * d0 + d1 * d1 + d2 * d2, red) * (1.0f / D_);
    float inv = rsqrtf(var + LN_EPS);
    float* yp = y + (size_t)row * D_;
    yp[threadIdx.x      ] = d0 * inv * s[threadIdx.x      ] + b[threadIdx.x      ];
    yp[threadIdx.x + 256] = d1 * inv * s[threadIdx.x + 256] + b[threadIdx.x + 256];
    yp[threadIdx.x + 512] = d2 * inv * s[threadIdx.x + 512] + b[threadIdx.x + 512];
}

__global__ void ln_split_kernel(const float* __restrict__ x,
                                const float* __restrict__ s,
                                const float* __restrict__ b,
                                __nv_bfloat16* __restrict__ yhi,
                                __nv_bfloat16* __restrict__ ylo) {
    __shared__ float red[33];
    int row = blockIdx.x;
    const float* xp = x + (size_t)row * D_;
    float v0 = xp[threadIdx.x];
    float v1 = xp[threadIdx.x + 256];
    float v2 = xp[threadIdx.x + 512];
    float mu = block_reduce_sum(v0 + v1 + v2, red) * (1.0f / D_);
    float d0 = v0 - mu, d1 = v1 - mu, d2 = v2 - mu;
    float var = block_reduce_sum(d0 * d0 + d1 * d1 + d2 * d2, red) * (1.0f / D_);
    float inv = rsqrtf(var + LN_EPS);
    size_t base = (size_t)row * D_;
    #pragma unroll
    for (int i = 0; i < 3; i++) {
        int c = threadIdx.x + i * 256;
        float dv = (i == 0 ? d0 : (i == 1 ? d1 : d2));
        float v = dv * inv * s[c] + b[c];
        __nv_bfloat16 h, l;
        split2(v, h, l);
        yhi[base + c] = h;
        ylo[base + c] = l;
    }
}

// ---------------- split-bf16 warp-mma GEMM (2 CTAs/SM, BK=32, 2-stage cp.async) ----------------
// C[M,N] = (Ahi+Alo)[M,K] @ (Whi+Wlo)[N,K]^T + bias
// EPI 0: write split bf16 ; EPI 1: gelu -> split bf16 ; EPI 2: +R -> fp32
template <int EPI>
__global__ __launch_bounds__(256, 2) void wmma_gemm(
    const __nv_bfloat16* __restrict__ Ahi, const __nv_bfloat16* __restrict__ Alo,
    const __nv_bfloat16* __restrict__ Whi, const __nv_bfloat16* __restrict__ Wlo,
    const float* __restrict__ bias, const float* __restrict__ R,
    float* __restrict__ C,
    __nv_bfloat16* __restrict__ Chi, __nv_bfloat16* __restrict__ Clo,
    int Ndim, int Kdim) {
    extern __shared__ char smem[];
    const unsigned sbase = smem_u32(smem);
    const int tid = threadIdx.x;
    const int lane = tid & 31;
    const int wid = tid >> 5;
    const int warp_m = wid & 1;          // 2 warp rows (64 M each)
    const int warp_n = wid >> 1;         // 4 warp cols (32 N each)
    const int bm = blockIdx.y * BM;
    const int bn = blockIdx.x * BN;
    const int NK = Kdim / BK;

    // per-thread cp.async mapping: 2 chunks per tile (128 rows x 32 bf16)
    const int r_ = tid >> 2, cc_ = tid & 3;
    const int r2_ = r_ + 64;
    const unsigned so1 = (unsigned)(r_ * (RS * 2) + cc_ * 16);
    const unsigned so2 = (unsigned)(r2_ * (RS * 2) + cc_ * 16);

    auto issue_stage = [&](int st) {
        const unsigned sb = sbase + (unsigned)((st & 1) * STAGE_B);
        const int k0 = st * BK;
        size_t a1 = (size_t)(bm + r_)  * Kdim + k0 + 8 * cc_;
        size_t a2 = (size_t)(bm + r2_) * Kdim + k0 + 8 * cc_;
        size_t b1 = (size_t)(bn + r_)  * Kdim + k0 + 8 * cc_;
        size_t b2 = (size_t)(bn + r2_) * Kdim + k0 + 8 * cc_;
        cp16(sb + so1,              Ahi + a1);
        cp16(sb + so2,              Ahi + a2);
        cp16(sb + TILE_B + so1,     Alo + a1);
        cp16(sb + TILE_B + so2,     Alo + a2);
        cp16(sb + 2 * TILE_B + so1, Whi + b1);
        cp16(sb + 2 * TILE_B + so2, Whi + b2);
        cp16(sb + 3 * TILE_B + so1, Wlo + b1);
        cp16(sb + 3 * TILE_B + so2, Wlo + b2);
        cp_commit();
    };

    const unsigned a_base = (unsigned)((warp_m * 64 + (lane & 15)) * (RS * 2) + (lane >> 4) * 16);
    const unsigned b_row = (unsigned)(warp_n * 32 + (lane & 7) + ((lane >> 4) << 3));
    const unsigned b_base = (unsigned)(b_row * (RS * 2) + (((lane >> 3) & 1) * 16));

    float acc[4][4][4];
    #pragma unroll
    for (int mt = 0; mt < 4; mt++)
        #pragma unroll
        for (int nt = 0; nt < 4; nt++)
            #pragma unroll
            for (int r = 0; r < 4; r++) acc[mt][nt][r] = 0.0f;

    issue_stage(0);

    for (int i = 0; i < NK; i++) {
        cp_wait<0>();
        __syncthreads();
        // safe for 2-stage: every thread has finished reading buffer (i+1)&1
        // (= iter i-1's buffer) once it passes this barrier.
        if (i + 1 < NK) issue_stage(i + 1);

        const unsigned tAhi = sbase + (unsigned)((i & 1) * STAGE_B);
        const unsigned tAlo = tAhi + TILE_B;
        const unsigned tBhi = tAlo + TILE_B;
        const unsigned tBlo = tBhi + TILE_B;

        #pragma unroll
        for (int ks = 0; ks < 2; ks++) {
            unsigned fbh[2][4], fbl[2][4];
            #pragma unroll
            for (int pr = 0; pr < 2; pr++) {
                unsigned bo = b_base + (unsigned)(pr * 16 * (RS * 2) + ks * 32);
                ldsm_x4(fbh[pr], tBhi + bo);
                ldsm_x4(fbl[pr], tBlo + bo);
            }
            #pragma unroll
            for (int mt = 0; mt < 4; mt++) {
                unsigned fah[4], fal[4];
                unsigned ao = a_base + (unsigned)(mt * 16 * (RS * 2) + ks * 32);
                ldsm_x4(fah, tAhi + ao);
                ldsm_x4(fal, tAlo + ao);
                #pragma unroll
                for (int nt = 0; nt < 4; nt++) {
                    const unsigned* bH = &fbh[nt >> 1][(nt & 1) * 2];
                    const unsigned* bL = &fbl[nt >> 1][(nt & 1) * 2];
                    mma_bf16(acc[mt][nt], fah, bH);
                    mma_bf16(acc[mt][nt], fah, bL);
                    mma_bf16(acc[mt][nt], fal, bH);
                }
            }
        }
    }

    // ---- epilogue ----
    const int g = lane >> 2, tg = lane & 3;
    #pragma unroll
    for (int mt = 0; mt < 4; mt++) {
        #pragma unroll
        for (int nt = 0; nt < 4; nt++) {
            int row0 = bm + warp_m * 64 + mt * 16 + g;
            int col  = bn + warp_n * 32 + nt * 8 + tg * 2;
            float2 bv = *(const float2*)(bias + col);
            float c0 = acc[mt][nt][0] + bv.x;
            float c1 = acc[mt][nt][1] + bv.y;
            float c2 = acc[mt][nt][2] + bv.x;
            float c3 = acc[mt][nt][3] + bv.y;
            size_t o0 = (size_t)row0 * Ndim + col;
            size_t o1 = o0 + (size_t)8 * Ndim;
            if (EPI == 2) {
                float2 r0 = *(const float2*)(R + o0);
                float2 r1 = *(const float2*)(R + o1);
                c0 += r0.x; c1 += r0.y; c2 += r1.x; c3 += r1.y;
                *(float2*)(C + o0) = make_float2(c0, c1);
                *(float2*)(C + o1) = make_float2(c2, c3);
            } else {
                if (EPI == 1) {
                    c0 = gelu_tanh(c0); c1 = gelu_tanh(c1);
                    c2 = gelu_tanh(c2); c3 = gelu_tanh(c3);
                }
                __nv_bfloat16 h0, l0v, h1, l1v, h2, l2v, h3, l3v;
                split2(c0, h0, l0v); split2(c1, h1, l1v);
                split2(c2, h2, l2v); split2(c3, h3, l3v);
                *(unsigned*)(Chi + o0) = pack_bf2(h0, h1);
                *(unsigned*)(Clo + o0) = pack_bf2(l0v, l1v);
                *(unsigned*)(Chi + o1) = pack_bf2(h2, h3);
                *(unsigned*)(Clo + o1) = pack_bf2(l2v, l3v);
            }
        }
    }
}

// ---------------- tensor-core flash attention (split bf16, R4 form) ----------------
__global__ __launch_bounds__(128) void attn_mma(
    const __nv_bfloat16* __restrict__ qh_, const __nv_bfloat16* __restrict__ ql_,
    __nv_bfloat16* __restrict__ oh_, __nv_bfloat16* __restrict__ ol_) {
    extern __shared__ char smem[];
    __nv_bfloat16* sb = (__nv_bfloat16*)smem;
    int* kcode = (int*)(smem + AT_CODE_B);
    const unsigned sbase = smem_u32(smem);
    const int h = blockIdx.y, b = blockIdx.z;
    const int q0 = blockIdx.x * 64;
    const int tid = threadIdx.x;
    const int lane = tid & 31;
    const int warp = tid >> 5;
    const int tg2 = (lane & 3) * 2;

    for (int idx = tid; idx < 64 * 8; idx += 128) {
        int r = idx >> 3, c = idx & 7;
        int gr = min(q0 + r, T_ - 1);
        size_t src = ((size_t)(b * T_ + gr)) * (3 * D_) + h * HD_ + c * 8;
        *(uint4*)&sb[AT_QH + r * ARS + c * 8] = *(const uint4*)(qh_ + src);
        *(uint4*)&sb[AT_QL + r * ARS + c * 8] = *(const uint4*)(ql_ + src);
    }
    __syncthreads();

    unsigned qfh[4][4], qfl[4][4];
    {
        unsigned rowoff = (unsigned)((warp * 16 + (lane & 15)) * (ARS * 2)) + (lane >> 4) * 16;
        #pragma unroll
        for (int ks = 0; ks < 4; ks++) {
            ldsm_x4(qfh[ks], sbase + AT_QH * 2 + rowoff + ks * 32);
            ldsm_x4(qfl[ks], sbase + AT_QL * 2 + rowoff + ks * 32);
        }
    }

    const int r0 = q0 + warp * 16 + (lane >> 2);
    const int r1 = r0 + 8;
    const int rc0 = min(r0, T_ - 1), rc1 = min(r1, T_ - 1);
    const int gq0 = tok_group(rc0), tq0 = tok_ts(rc0);
    const int gq1 = tok_group(rc1), tq1 = tok_ts(rc1);

    float m0 = -1e30f, m1 = -1e30f, l0 = 0.0f, l1 = 0.0f;
    float o[8][4];
    #pragma unroll
    for (int nt = 0; nt < 8; nt++)
        #pragma unroll
        for (int r = 0; r < 4; r++) o[nt][r] = 0.0f;

    const int rlast = min(q0 + 63, T_ - 1);
    const int kmax = P_ + (tok_ts(rlast) + 1) * TPS;

    const unsigned kb = (unsigned)(((lane & 7) + ((lane >> 4) << 3)) * (ARS * 2)) +
                        ((lane >> 3) & 1) * 16;

    for (int k0 = 0; k0 < kmax; k0 += 64) {
        __syncthreads();
        for (int idx = tid; idx < 64 * 8; idx += 128) {
            int r = idx >> 3, c = idx & 7;
            int kr = k0 + r;
            uint4 z = make_uint4(0, 0, 0, 0);
            uint4 kvh = z, kvl = z, vvh = z, vvl = z;
            if (kr < T_) {
                size_t src = ((size_t)(b * T_ + kr)) * (3 * D_) + D_ + h * HD_ + c * 8;
                kvh = *(const uint4*)(qh_ + src);
                kvl = *(const uint4*)(ql_ + src);
                vvh = *(const uint4*)(qh_ + src + D_);
                vvl = *(const uint4*)(ql_ + src + D_);
            }
            *(uint4*)&sb[AT_KH + r * ARS + c * 8] = kvh;
            *(uint4*)&sb[AT_KL + r * ARS + c * 8] = kvl;
            *(uint4*)&sb[AT_VH + r * ARS + c * 8] = vvh;
            *(uint4*)&sb[AT_VL + r * ARS + c * 8] = vvl;
        }
        if (tid < 64) {
            int kg = k0 + tid;
            kcode[tid] = (kg < kmax && kg < T_)
                       ? ((tok_ts(kg) << 2) | tok_group(kg))
                       : ((0x3FFF << 2) | 3);
        }
        __syncthreads();

        float s[8][4];
        #pragma unroll
        for (int nt = 0; nt < 8; nt++)
            #pragma unroll
            for (int r = 0; r < 4; r++) s[nt][r] = 0.0f;

        #pragma unroll
        for (int kg = 0; kg < 4; kg++) {
            #pragma unroll
            for (int ks = 0; ks < 4; ks++) {
                unsigned kh[4], kl[4];
                unsigned addr = sbase + kb + (unsigned)(kg * 16 * (ARS * 2)) + ks * 32;
                ldsm_x4(kh, addr + AT_KH * 2);
                ldsm_x4(kl, addr + AT_KL * 2);
                #pragma unroll
                for (int half = 0; half < 2; half++) {
                    int nt = kg * 2 + half;
                    mma_bf16(s[nt], qfh[ks], &kh[half * 2]);
                    mma_bf16(s[nt], qfh[ks], &kl[half * 2]);
                    mma_bf16(s[nt], qfl[ks], &kh[half * 2]);
                }
            }
        }

        #pragma unroll
        for (int nt = 0; nt < 8; nt++) {
            int kc0 = kcode[nt * 8 + tg2];
            int kc1 = kcode[nt * 8 + tg2 + 1];
            s[nt][0] = allow_code(gq0, tq0, kc0) ? s[nt][0] * ATT_SCALE : -1e30f;
            s[nt][1] = allow_code(gq0, tq0, kc1) ? s[nt][1] * ATT_SCALE : -1e30f;
            s[nt][2] = allow_code(gq1, tq1, kc0) ? s[nt][2] * ATT_SCALE : -1e30f;
            s[nt][3] = allow_code(gq1, tq1, kc1) ? s[nt][3] * ATT_SCALE : -1e30f;
        }

        float mx0 = -1e30f, mx1 = -1e30f;
        #pragma unroll
        for (int nt = 0; nt < 8; nt++) {
            mx0 = fmaxf(mx0, fmaxf(s[nt][0], s[nt][1]));
            mx1 = fmaxf(mx1, fmaxf(s[nt][2], s[nt][3]));
        }
        mx0 = fmaxf(mx0, __shfl_xor_sync(0xffffffffu, mx0, 1));
        mx0 = fmaxf(mx0, __shfl_xor_sync(0xffffffffu, mx0, 2));
        mx1 = fmaxf(mx1, __shfl_xor_sync(0xffffffffu, mx1, 1));
        mx1 = fmaxf(mx1, __shfl_xor_sync(0xffffffffu, mx1, 2));
        float mn0 = fmaxf(m0, mx0), mn1 = fmaxf(m1, mx1);
        float corr0 = __expf(m0 - mn0), corr1 = __expf(m1 - mn1);
        m0 = mn0; m1 = mn1;
        l0 *= corr0; l1 *= corr1;
        #pragma unroll
        for (int nt = 0; nt < 8; nt++) {
            o[nt][0] *= corr0; o[nt][1] *= corr0;
            o[nt][2] *= corr1; o[nt][3] *= corr1;
        }

        #pragma unroll
        for (int kv = 0; kv < 4; kv++) {
            unsigned ph[4], pl[4];
            #pragma unroll
            for (int half = 0; half < 2; half++) {
                int nt = kv * 2 + half;
                float p0 = __expf(s[nt][0] - m0);
                float p1 = __expf(s[nt][1] - m0);
                float p2 = __expf(s[nt][2] - m1);
                float p3 = __expf(s[nt][3] - m1);
                l0 += p0 + p1;
                l1 += p2 + p3;
                __nv_bfloat16 h0, lo0, h1, lo1, h2, lo2, h3, lo3;
                split2(p0, h0, lo0); split2(p1, h1, lo1);
                split2(p2, h2, lo2); split2(p3, h3, lo3);
                ph[half * 2 + 0] = pack_bf2(h0, h1);
                ph[half * 2 + 1] = pack_bf2(h2, h3);
                pl[half * 2 + 0] = pack_bf2(lo0, lo1);
                pl[half * 2 + 1] = pack_bf2(lo2, lo3);
            }
            #pragma unroll
            for (int dg = 0; dg < 4; dg++) {
                unsigned vh[4], vl[4];
                unsigned addr = sbase + kb + (unsigned)(kv * 16 * (ARS * 2)) + dg * 32;
                ldsm_x4t(vh, addr + AT_VH * 2);
                ldsm_x4t(vl, addr + AT_VL * 2);
                #pragma unroll
                for (int half = 0; half < 2; half++) {
                    int nt = dg * 2 + half;
                    unsigned bhp[2] = {vh[half], vh[2 + half]};
                    unsigned blp[2] = {vl[half], vl[2 + half]};
                    mma_bf16(o[nt], ph, bhp);
                    mma_bf16(o[nt], ph, blp);
                    mma_bf16(o[nt], pl, bhp);
                }
            }
        }
    }

    l0 += __shfl_xor_sync(0xffffffffu, l0, 1);
    l0 += __shfl_xor_sync(0xffffffffu, l0, 2);
    l1 += __shfl_xor_sync(0xffffffffu, l1, 1);
    l1 += __shfl_xor_sync(0xffffffffu, l1, 2);
    float li0 = 1.0f / l0, li1 = 1.0f / l1;

    #pragma unroll
    for (int nt = 0; nt < 8; nt++) {
        int d = h * HD_ + nt * 8 + tg2;
        if (r0 < T_) {
            size_t off = ((size_t)(b * T_ + r0)) * D_ + d;
            float v0 = o[nt][0] * li0, v1 = o[nt][1] * li0;
            __nv_bfloat16 h0, lo0, h1, lo1;
            split2(v0, h0, lo0); split2(v1, h1, lo1);
            *(unsigned*)(oh_ + off) = pack_bf2(h0, h1);
            *(unsigned*)(ol_ + off) = pack_bf2(lo0, lo1);
        }
        if (r1 < T_) {
            size_t off = ((size_t)(b * T_ + r1)) * D_ + d;
            float v2 = o[nt][2] * li1, v3 = o[nt][3] * li1;
            __nv_bfloat16 h2, lo2, h3, lo3;
            split2(v2, h2, lo2); split2(v3, h3, lo3);
            *(unsigned*)(oh_ + off) = pack_bf2(h2, h3);
            *(unsigned*)(ol_ + off) = pack_bf2(lo2, lo3);
        }
    }
}

// ---------------- host orchestration ----------------
extern "C" void kernel_launch(void* const* d_in, const int* in_sizes, int n_in,
                              void* d_out, int out_size) {
    (void)in_sizes; (void)n_in; (void)out_size;

    const float* prefix = (const float*)d_in[0];
    const float* obs    = (const float*)d_in[2];
    const float* rdo    = (const float*)d_in[4];
    const float* ln1_s  = (const float*)d_in[6];
    const float* ln1_b  = (const float*)d_in[7];
    const float* wqkv   = (const float*)d_in[8];
    const float* bqkv   = (const float*)d_in[9];
    const float* wo     = (const float*)d_in[10];
    const float* bo     = (const float*)d_in[11];
    const float* ln2_s  = (const float*)d_in[12];
    const float* ln2_b  = (const float*)d_in[13];
    const float* w1     = (const float*)d_in[14];
    const float* b1     = (const float*)d_in[15];
    const float* w2     = (const float*)d_in[16];
    const float* b2     = (const float*)d_in[17];
    const float* lnf_s  = (const float*)d_in[18];
    const float* lnf_b  = (const float*)d_in[19];
    float* out = (float*)d_out;

    float* x;
    __nv_bfloat16 *yhi, *ylo, *qkvhi, *qkvlo, *atthi, *attlo, *ffnhi, *ffnlo;
    __nv_bfloat16 *wqkvT_hi, *wqkvT_lo, *woT_hi, *woT_lo, *w1T_hi, *w1T_lo, *w2T_hi, *w2T_lo;
    cudaGetSymbolAddress((void**)&x,     g_x);
    cudaGetSymbolAddress((void**)&yhi,   g_y_hi);
    cudaGetSymbolAddress((void**)&ylo,   g_y_lo);
    cudaGetSymbolAddress((void**)&qkvhi, g_qkv_hi);
    cudaGetSymbolAddress((void**)&qkvlo, g_qkv_lo);
    cudaGetSymbolAddress((void**)&atthi, g_att_hi);
    cudaGetSymbolAddress((void**)&attlo, g_att_lo);
    cudaGetSymbolAddress((void**)&ffnhi, g_ffn_hi);
    cudaGetSymbolAddress((void**)&ffnlo, g_ffn_lo);
    cudaGetSymbolAddress((void**)&wqkvT_hi, g_wqkvT_hi);
    cudaGetSymbolAddress((void**)&wqkvT_lo, g_wqkvT_lo);
    cudaGetSymbolAddress((void**)&woT_hi,   g_woT_hi);
    cudaGetSymbolAddress((void**)&woT_lo,   g_woT_lo);
    cudaGetSymbolAddress((void**)&w1T_hi,   g_w1T_hi);
    cudaGetSymbolAddress((void**)&w1T_lo,   g_w1T_lo);
    cudaGetSymbolAddress((void**)&w2T_hi,   g_w2T_hi);
    cudaGetSymbolAddress((void**)&w2T_lo,   g_w2T_lo);

    cudaFuncSetAttribute(wmma_gemm<0>, cudaFuncAttributeMaxDynamicSharedMemorySize, SMEM_GEMM);
    cudaFuncSetAttribute(wmma_gemm<1>, cudaFuncAttributeMaxDynamicSharedMemorySize, SMEM_GEMM);
    cudaFuncSetAttribute(wmma_gemm<2>, cudaFuncAttributeMaxDynamicSharedMemorySize, SMEM_GEMM);
    cudaFuncSetAttribute(attn_mma, cudaFuncAttributeMaxDynamicSharedMemorySize, ATTN_SMEM);

    assemble_kernel<<<2048, 256>>>(prefix, obs, rdo);

    wsplit_all_kernel<<<dim3(6912, L_), dim3(32, 8)>>>(
        wqkv, wo, w1, w2,
        wqkvT_hi, wqkvT_lo, woT_hi, woT_lo, w1T_hi, w1T_lo, w2T_hi, w2T_lo);

    const dim3 g_qkv_grid(3 * D_ / BN, M_ / BM);   // (18, 86)
    const dim3 g_wo_grid (D_ / BN,     M_ / BM);   // (6, 86)
    const dim3 g_w1_grid (F_ / BN,     M_ / BM);   // (24, 86)
    const dim3 g_attn((T_ + 63) / 64, NH_, B_);    // (22, 12, 8)

    for (int l = 0; l < L_; l++) {
        ln_split_kernel<<<M_, 256>>>(x, ln1_s + (size_t)l * D_, ln1_b + (size_t)l * D_, yhi, ylo);
        wmma_gemm<0><<<g_qkv_grid, 256, SMEM_GEMM>>>(
            yhi, ylo,
            wqkvT_hi + (size_t)l * 3 * D_ * D_, wqkvT_lo + (size_t)l * 3 * D_ * D_,
            bqkv + (size_t)l * 3 * D_, nullptr, nullptr, qkvhi, qkvlo, 3 * D_, D_);
        attn_mma<<<g_attn, 128, ATTN_SMEM>>>(qkvhi, qkvlo, atthi, attlo);
        wmma_gemm<2><<<g_wo_grid, 256, SMEM_GEMM>>>(
            atthi, attlo,
            woT_hi + (size_t)l * D_ * D_, woT_lo + (size_t)l * D_ * D_,
            bo + (size_t)l * D_, x, x, nullptr, nullptr, D_, D_);
        ln_split_kernel<<<M_, 256>>>(x, ln2_s + (size_t)l * D_, ln2_b + (size_t)l * D_, yhi, ylo);
        wmma_gemm<1><<<g_w1_grid, 256, SMEM_GEMM>>>(
            yhi, ylo,
            w1T_hi + (size_t)l * F_ * D_, w1T_lo + (size_t)l * F_ * D_,
            b1 + (size_t)l * F_, nullptr, nullptr, ffnhi, ffnlo, F_, D_);
        wmma_gemm<2><<<g_wo_grid, 256, SMEM_GEMM>>>(
            ffnhi, ffnlo,
            w2T_hi + (size_t)l * D_ * F_, w2T_lo + (size_t)l * D_ * F_,
            b2 + (size_t)l * D_, x, x, nullptr, nullptr, D_, F_);
    }

    ln_kernel<<<M_, 256>>>(x, lnf_s, lnf_b, out);
}